// round 10
// baseline (speedup 1.0000x reference)
#include <cuda_runtime.h>
#include <cuda_bf16.h>
#include <math.h>
#include <stdint.h>

#define HID   1024
#define NH    16
#define HD    64
#define NP    4
#define BATCH 4
#define SEQ   1024

// ---------------- scratch (device globals; no allocation allowed) ----------------
__device__ float g_LW[BATCH * NP];

__device__ __nv_bfloat16 g_Phi[(size_t)NP * BATCH * SEQ * HID];
__device__ __nv_bfloat16 g_Plo[(size_t)NP * BATCH * SEQ * HID];
__device__ __nv_bfloat16 g_Hhi[(size_t)BATCH * SEQ * HID];
__device__ __nv_bfloat16 g_Hlo[(size_t)BATCH * SEQ * HID];
__device__ __nv_bfloat16 g_Chi[(size_t)BATCH * SEQ * HID];
__device__ __nv_bfloat16 g_Clo[(size_t)BATCH * SEQ * HID];
__device__ __nv_bfloat16 g_Wthi[4][(size_t)HID * HID];
__device__ __nv_bfloat16 g_Wtlo[4][(size_t)HID * HID];

__device__ __nv_bfloat16 g_Qhi[(size_t)BATCH * NH * SEQ * HD];
__device__ __nv_bfloat16 g_Qlo[(size_t)BATCH * NH * SEQ * HD];
__device__ __nv_bfloat16 g_Khi[(size_t)NP * BATCH * NH * SEQ * HD];
__device__ __nv_bfloat16 g_Klo[(size_t)NP * BATCH * NH * SEQ * HD];
__device__ __nv_bfloat16 g_Vhi[(size_t)NP * BATCH * NH * SEQ * HD];
__device__ __nv_bfloat16 g_Vlo[(size_t)NP * BATCH * NH * SEQ * HD];

// ---------------- helpers ----------------
static __device__ __forceinline__ uint32_t s2u(const void* p) {
    uint32_t a;
    asm("{ .reg .u64 t; cvta.to.shared.u64 t, %1; cvt.u32.u64 %0, t; }" : "=r"(a) : "l"(p));
    return a;
}
static __device__ __forceinline__ void ldm_x4(uint32_t addr, uint32_t r[4]) {
    asm volatile("ldmatrix.sync.aligned.m8n8.x4.shared.b16 {%0,%1,%2,%3}, [%4];"
                 : "=r"(r[0]), "=r"(r[1]), "=r"(r[2]), "=r"(r[3]) : "r"(addr));
}
static __device__ __forceinline__ void ldm_x4t(uint32_t addr, uint32_t r[4]) {
    asm volatile("ldmatrix.sync.aligned.m8n8.x4.trans.shared.b16 {%0,%1,%2,%3}, [%4];"
                 : "=r"(r[0]), "=r"(r[1]), "=r"(r[2]), "=r"(r[3]) : "r"(addr));
}
static __device__ __forceinline__ void mma16816(float* c, const uint32_t a[4],
                                                uint32_t b0, uint32_t b1) {
    asm volatile(
        "mma.sync.aligned.m16n8k16.row.col.f32.bf16.bf16.f32 "
        "{%0,%1,%2,%3}, {%4,%5,%6,%7}, {%8,%9}, {%0,%1,%2,%3};"
        : "+f"(c[0]), "+f"(c[1]), "+f"(c[2]), "+f"(c[3])
        : "r"(a[0]), "r"(a[1]), "r"(a[2]), "r"(a[3]), "r"(b0), "r"(b1));
}
static __device__ __forceinline__ uint32_t pack_bf16(float x, float y) {
    __nv_bfloat16 a = __float2bfloat16(x), b = __float2bfloat16(y);
    return (uint32_t)__bfloat16_as_ushort(a) | ((uint32_t)__bfloat16_as_ushort(b) << 16);
}
static __device__ __forceinline__ void cp16(uint32_t saddr, const void* g) {
    asm volatile("cp.async.cg.shared.global [%0], [%1], 16;" :: "r"(saddr), "l"(g));
}
#define CP_COMMIT() asm volatile("cp.async.commit_group;" ::: "memory")
#define CP_WAIT1()  asm volatile("cp.async.wait_group 1;" ::: "memory")
#define CP_WAIT0()  asm volatile("cp.async.wait_group 0;" ::: "memory")

// ---------------- gating ----------------
__global__ void gating_kernel(const float* __restrict__ hs,
                              const float* __restrict__ wg,
                              float* __restrict__ lw) {
    int b = blockIdx.x;
    int t = threadIdx.x;
    const float* p = hs + (size_t)b * SEQ * HID + t;
    float s = 0.f;
    for (int i = 0; i < SEQ; i++) s += p[(size_t)i * HID];
    s *= (1.0f / SEQ);

    float lg[NP];
#pragma unroll
    for (int k = 0; k < NP; k++) lg[k] = s * wg[t * NP + k];

    __shared__ float red[NP][32];
    int lane = t & 31, w = t >> 5;
#pragma unroll
    for (int k = 0; k < NP; k++) {
        float v = lg[k];
#pragma unroll
        for (int o = 16; o; o >>= 1) v += __shfl_xor_sync(~0u, v, o);
        if (lane == 0) red[k][w] = v;
    }
    __syncthreads();
    if (w == 0) {
#pragma unroll
        for (int k = 0; k < NP; k++) {
            float v = red[k][lane];
#pragma unroll
            for (int o = 16; o; o >>= 1) v += __shfl_xor_sync(~0u, v, o);
            if (lane == 0) red[k][0] = v;
        }
    }
    __syncthreads();
    if (t == 0) {
        float m = red[0][0];
#pragma unroll
        for (int k = 1; k < NP; k++) m = fmaxf(m, red[k][0]);
        float e[NP], se = 0.f;
#pragma unroll
        for (int k = 0; k < NP; k++) { e[k] = expf(red[k][0] - m); se += e[k]; }
        float inv = 1.0f / se;
#pragma unroll
        for (int k = 0; k < NP; k++) lw[b * NP + k] = e[k] * inv;
    }
}

// ---------------- fp32 -> (bf16 hi, bf16 lo) split ----------------
__global__ void split_kernel(const float* __restrict__ in,
                             __nv_bfloat16* __restrict__ hi,
                             __nv_bfloat16* __restrict__ lo, int n4) {
    int i = blockIdx.x * 256 + threadIdx.x;
    if (i >= n4) return;
    float4 v = ((const float4*)in)[i];
    float x[4] = {v.x, v.y, v.z, v.w};
    uint32_t ph[2], pl[2];
#pragma unroll
    for (int j = 0; j < 2; j++) {
        __nv_bfloat16 h0 = __float2bfloat16(x[2 * j]);
        __nv_bfloat16 h1 = __float2bfloat16(x[2 * j + 1]);
        __nv_bfloat16 l0 = __float2bfloat16(x[2 * j] - __bfloat162float(h0));
        __nv_bfloat16 l1 = __float2bfloat16(x[2 * j + 1] - __bfloat162float(h1));
        ph[j] = (uint32_t)__bfloat16_as_ushort(h0) | ((uint32_t)__bfloat16_as_ushort(h1) << 16);
        pl[j] = (uint32_t)__bfloat16_as_ushort(l0) | ((uint32_t)__bfloat16_as_ushort(l1) << 16);
    }
    ((uint2*)hi)[i] = make_uint2(ph[0], ph[1]);
    ((uint2*)lo)[i] = make_uint2(pl[0], pl[1]);
}

// ---------------- W [K,N] fp32 -> Wt [N,K] bf16 hi/lo ----------------
__global__ void wsplit_kernel(const float* __restrict__ W,
                              __nv_bfloat16* __restrict__ hi,
                              __nv_bfloat16* __restrict__ lo) {
    __shared__ float tile[32][33];
    int k0 = blockIdx.x * 32, n0 = blockIdx.y * 32;
    for (int j = threadIdx.y; j < 32; j += 8)
        tile[j][threadIdx.x] = W[(size_t)(k0 + j) * HID + n0 + threadIdx.x];
    __syncthreads();
    for (int j = threadIdx.y; j < 32; j += 8) {
        float x = tile[threadIdx.x][j];
        __nv_bfloat16 h = __float2bfloat16(x);
        __nv_bfloat16 l = __float2bfloat16(x - __bfloat162float(h));
        size_t o = (size_t)(n0 + j) * HID + k0 + threadIdx.x;
        hi[o] = h;
        lo[o] = l;
    }
}

// ---------------- HMMA split-bf16 GEMM, 128x128 tile, KC=32, cp.async 2-stage ----------------
#define MT 128
#define NT 128
#define KC 32
#define NCHUNK (HID / KC)
#define APAD 40

#define SM_BIAS  0
#define SM_INVF  512
#define SM_BUF   1024
#define ARR      (128 * APAD * 2)
#define OFF_AHI  0
#define OFF_ALO  ARR
#define OFF_BHI  (2 * ARR)
#define OFF_BLO  (3 * ARR)
#define STAGE    (4 * ARR)
#define SM_END   (SM_BUF + 2 * STAGE)  // 82944
#define SM_CS    SM_BUF

static __device__ __forceinline__ void gemm_issue(
    uint32_t sbase, int tid,
    const __nv_bfloat16* __restrict__ Ahi, const __nv_bfloat16* __restrict__ Alo,
    const __nv_bfloat16* __restrict__ Bhi, const __nv_bfloat16* __restrict__ Blo,
    size_t ab, size_t bb) {
#pragma unroll
    for (int it = 0; it < 2; it++) {
        int t2 = tid + it * 256;
        int r = t2 >> 2, e0 = (t2 & 3) * 8;
        uint32_t so = (uint32_t)(r * APAD + e0) * 2;
        size_t ga = ab + (size_t)r * HID + e0;
        size_t gb = bb + (size_t)r * HID + e0;
        cp16(sbase + OFF_AHI + so, Ahi + ga);
        cp16(sbase + OFF_ALO + so, Alo + ga);
        cp16(sbase + OFF_BHI + so, Bhi + gb);
        cp16(sbase + OFF_BLO + so, Blo + gb);
    }
    CP_COMMIT();
}

template <int MODE>
__global__ void __launch_bounds__(256, 2)
gemm_hmma(const __nv_bfloat16* __restrict__ Ahi, const __nv_bfloat16* __restrict__ Alo,
          const __nv_bfloat16* __restrict__ Bhi, const __nv_bfloat16* __restrict__ Blo,
          const float* __restrict__ bias, float* __restrict__ out,
          __nv_bfloat16* __restrict__ ohi, __nv_bfloat16* __restrict__ olo) {
    extern __shared__ __align__(16) char sm[];
    const uint32_t smb = s2u(sm);
    float* bsm  = (float*)(sm + SM_BIAS);
    float* invf = (float*)(sm + SM_INVF);

    const int tid = threadIdx.x;
    const int wid = tid >> 5, lane = tid & 31;
    const int g = lane >> 2, tig = lane & 3;
    const int warp_m = wid >> 2, warp_n = wid & 3;
    const int m_base = warp_m * 64, n_base = warp_n * 32;
    const int m0 = blockIdx.x * MT;
    const int col0 = blockIdx.y * NT;

    if (tid < 128) bsm[tid] = bias[col0 + tid];
    if (MODE == 1 && tid < 32)
        invf[tid] = powf(10000.0f, -(float)tid * (1.0f / 32.0f));

    float acc[4][4][4];
#pragma unroll
    for (int a = 0; a < 4; a++)
#pragma unroll
        for (int b = 0; b < 4; b++)
#pragma unroll
            for (int c = 0; c < 4; c++) acc[a][b][c] = 0.f;

    const int a_row = lane & 15, a_col8 = (lane >> 4) * 8;
    const int b_nrow = (lane & 7) + ((lane >> 4) << 3);
    const int b_k8 = ((lane >> 3) & 1) * 8;

    const size_t abase = (size_t)m0 * HID;
    const size_t bbase = (size_t)col0 * HID;

    gemm_issue(smb + SM_BUF, tid, Ahi, Alo, Bhi, Blo, abase, bbase);

    for (int kc = 0; kc < NCHUNK; kc++) {
        if (kc + 1 < NCHUNK) {
            gemm_issue(smb + SM_BUF + ((kc + 1) & 1) * STAGE, tid, Ahi, Alo, Bhi, Blo,
                       abase + (kc + 1) * KC, bbase + (kc + 1) * KC);
            CP_WAIT1();
        } else {
            CP_WAIT0();
        }
        __syncthreads();

        const uint32_t sb = smb + SM_BUF + (kc & 1) * STAGE;
#pragma unroll
        for (int k16 = 0; k16 < KC / 16; k16++) {
            uint32_t bhif[2][4], blof[2][4];
#pragma unroll
            for (int nt2 = 0; nt2 < 2; nt2++) {
                uint32_t off = (uint32_t)((n_base + nt2 * 16 + b_nrow) * APAD
                                          + k16 * 16 + b_k8) * 2;
                ldm_x4(sb + OFF_BHI + off, bhif[nt2]);
                ldm_x4(sb + OFF_BLO + off, blof[nt2]);
            }
#pragma unroll
            for (int mt = 0; mt < 4; mt++) {
                uint32_t ahif[4], alof[4];
                uint32_t off = (uint32_t)((m_base + mt * 16 + a_row) * APAD
                                          + k16 * 16 + a_col8) * 2;
                ldm_x4(sb + OFF_AHI + off, ahif);
                ldm_x4(sb + OFF_ALO + off, alof);
#pragma unroll
                for (int nt = 0; nt < 4; nt++) {
                    uint32_t b0h = bhif[nt >> 1][(nt & 1) * 2];
                    uint32_t b1h = bhif[nt >> 1][(nt & 1) * 2 + 1];
                    uint32_t b0l = blof[nt >> 1][(nt & 1) * 2];
                    uint32_t b1l = blof[nt >> 1][(nt & 1) * 2 + 1];
                    mma16816(acc[mt][nt], ahif, b0h, b1h);
                    mma16816(acc[mt][nt], ahif, b0l, b1l);
                    mma16816(acc[mt][nt], alof, b0h, b1h);
                }
            }
        }
        __syncthreads();
    }

    // ---------------- epilogue ----------------
    if (MODE == 1) {
        float* Cs = (float*)(sm + SM_CS);
#pragma unroll
        for (int mt = 0; mt < 4; mt++)
#pragma unroll
            for (int i2 = 0; i2 < 2; i2++) {
                int r = m_base + mt * 16 + g + i2 * 8;
#pragma unroll
                for (int nt = 0; nt < 4; nt++) {
                    int c = n_base + nt * 8 + 2 * tig;
                    Cs[r * 130 + c]     = acc[mt][nt][i2 * 2]     + bsm[c];
                    Cs[r * 130 + c + 1] = acc[mt][nt][i2 * 2 + 1] + bsm[c + 1];
                }
            }
        __syncthreads();
        const int seg = m0 >> 10;
        const int sbase2 = m0 & (SEQ - 1);
#pragma unroll
        for (int it = 0; it < 32; it++) {
            int idx = tid + it * 256;
            int r = idx >> 6, q = idx & 63;
            int h2 = q >> 5, d = q & 31;
            float c1 = Cs[r * 130 + h2 * 64 + d];
            float c2 = Cs[r * 130 + h2 * 64 + d + 32];
            int s = sbase2 + r;
            float sn, cs;
            sincosf((float)s * invf[d], &sn, &cs);
            int hh = blockIdx.y * 2 + h2;
            size_t base = ((size_t)(seg * NH + hh) * SEQ + s) << 6;
            float o1 = c1 * cs - c2 * sn;
            float o2 = c1 * sn + c2 * cs;
            __nv_bfloat16 h1 = __float2bfloat16(o1);
            __nv_bfloat16 h2b = __float2bfloat16(o2);
            ohi[base + d]      = h1;
            ohi[base + d + 32] = h2b;
            olo[base + d]      = __float2bfloat16(o1 - __bfloat162float(h1));
            olo[base + d + 32] = __float2bfloat16(o2 - __bfloat162float(h2b));
        }
    } else {
        const int seg = m0 >> 10;
        const int sbase2 = m0 & (SEQ - 1);
#pragma unroll
        for (int mt = 0; mt < 4; mt++)
#pragma unroll
            for (int i2 = 0; i2 < 2; i2++) {
                int rloc = m_base + mt * 16 + g + i2 * 8;
#pragma unroll
                for (int nt = 0; nt < 4; nt++) {
                    int c = n_base + nt * 8 + 2 * tig;
                    float vx = acc[mt][nt][i2 * 2]     + bsm[c];
                    float vy = acc[mt][nt][i2 * 2 + 1] + bsm[c + 1];
                    if (MODE == 0) {
                        *(float2*)&out[(size_t)(m0 + rloc) * HID + col0 + c] = make_float2(vx, vy);
                    } else {
                        int hh = blockIdx.y * 2 + (c >> 6);
                        int d = c & 63;
                        int s = sbase2 + rloc;
                        size_t off = (((size_t)(seg * NH + hh) * SEQ + s) << 6) + d;
                        __nv_bfloat16 hx = __float2bfloat16(vx);
                        __nv_bfloat16 hy = __float2bfloat16(vy);
                        uint32_t hp = (uint32_t)__bfloat16_as_ushort(hx) |
                                      ((uint32_t)__bfloat16_as_ushort(hy) << 16);
                        uint32_t lp = pack_bf16(vx - __bfloat162float(hx),
                                                vy - __bfloat162float(hy));
                        *(uint32_t*)&ohi[off] = hp;
                        *(uint32_t*)&olo[off] = lp;
                    }
                }
            }
    }
}

// ---------------- HMMA flash attention, 2 CTAs/SM target ----------------
#define VPAD 72
#define AS_QHI 0
#define AS_QLO (128 * VPAD * 2)
#define AS_KHI (2 * 128 * VPAD * 2)                 // 36864
#define AS_KLO (AS_KHI + 64 * VPAD * 2)
#define AS_VHI (AS_KLO + 64 * VPAD * 2)
#define AS_VLO (AS_VHI + 64 * VPAD * 2)
#define AS_END (AS_VLO + 64 * VPAD * 2)             // 73728

__global__ void __launch_bounds__(256, 2)
attn_hmma(const __nv_bfloat16* __restrict__ Qhi, const __nv_bfloat16* __restrict__ Qlo,
          const __nv_bfloat16* __restrict__ Khi, const __nv_bfloat16* __restrict__ Klo,
          const __nv_bfloat16* __restrict__ Vhi, const __nv_bfloat16* __restrict__ Vlo,
          const float* __restrict__ LW,
          __nv_bfloat16* __restrict__ Chi, __nv_bfloat16* __restrict__ Clo) {
    extern __shared__ __align__(16) char sm[];
    const uint32_t smb = s2u(sm);
    const int tid = threadIdx.x;
    const int wid = tid >> 5, lane = tid & 31;
    const int g = lane >> 2, t = lane & 3;
    const int qt = blockIdx.x, hh = blockIdx.y, b = blockIdx.z;
    const int s0 = qt * 128;

    // load Q tile (hi/lo)
    {
        const __nv_bfloat16* qh = Qhi + (((size_t)(b * NH + hh) * SEQ + s0) << 6);
        const __nv_bfloat16* ql = Qlo + (((size_t)(b * NH + hh) * SEQ + s0) << 6);
        for (int i = tid; i < 128 * 8; i += 256) {
            int r = i >> 3, c8 = (i & 7) * 8;
            uint32_t so = (uint32_t)(r * VPAD + c8) * 2;
            *(uint4*)(sm + AS_QHI + so) = *(const uint4*)(qh + ((size_t)r << 6) + c8);
            *(uint4*)(sm + AS_QLO + so) = *(const uint4*)(ql + ((size_t)r << 6) + c8);
        }
    }
    __syncthreads();

    // Q fragments resident in registers
    uint32_t qhf[4][4], qlf[4][4];
    {
        const int a_row = lane & 15, a_c8 = (lane >> 4) * 8;
#pragma unroll
        for (int k16 = 0; k16 < 4; k16++) {
            uint32_t off = (uint32_t)((wid * 16 + a_row) * VPAD + k16 * 16 + a_c8) * 2;
            ldm_x4(smb + AS_QHI + off, qhf[k16]);
            ldm_x4(smb + AS_QLO + off, qlf[k16]);
        }
    }

    const int b_nrow = (lane & 7) + ((lane >> 4) << 3);
    const int b_k8 = ((lane >> 3) & 1) * 8;
    const int v_row = (lane & 7) + (((lane >> 3) & 1) << 3);
    const int v_c8 = (lane >> 4) * 8;

    float comb[8][4];
#pragma unroll
    for (int n = 0; n < 8; n++)
#pragma unroll
        for (int i = 0; i < 4; i++) comb[n][i] = 0.f;

    for (int p = 0; p < NP; p++) {
        float m0 = -1e30f, m1 = -1e30f, l0 = 0.f, l1 = 0.f;
        float accO[8][4];
#pragma unroll
        for (int n = 0; n < 8; n++)
#pragma unroll
            for (int i = 0; i < 4; i++) accO[n][i] = 0.f;

        const size_t kvbase = ((size_t)((p * BATCH + b) * NH + hh) * SEQ) << 6;

        for (int kt = 0; kt < SEQ / 64; kt++) {
            __syncthreads();
            {
                const size_t tb = kvbase + ((size_t)(kt * 64) << 6);
                for (int i = tid; i < 64 * 8; i += 256) {
                    int r = i >> 3, c8 = (i & 7) * 8;
                    uint32_t so = (uint32_t)(r * VPAD + c8) * 2;
                    size_t go = tb + ((size_t)r << 6) + c8;
                    *(uint4*)(sm + AS_KHI + so) = *(const uint4*)(Khi + go);
                    *(uint4*)(sm + AS_KLO + so) = *(const uint4*)(Klo + go);
                    *(uint4*)(sm + AS_VHI + so) = *(const uint4*)(Vhi + go);
                    *(uint4*)(sm + AS_VLO + so) = *(const uint4*)(Vlo + go);
                }
            }
            __syncthreads();

            // S = Q K^T (3-term split)
            float s[8][4];
#pragma unroll
            for (int n = 0; n < 8; n++)
#pragma unroll
                for (int i = 0; i < 4; i++) s[n][i] = 0.f;
#pragma unroll
            for (int k16 = 0; k16 < 4; k16++) {
#pragma unroll
                for (int j = 0; j < 4; j++) {
                    uint32_t kh[4], kl[4];
                    uint32_t off = (uint32_t)((j * 16 + b_nrow) * VPAD + k16 * 16 + b_k8) * 2;
                    ldm_x4(smb + AS_KHI + off, kh);
                    ldm_x4(smb + AS_KLO + off, kl);
#pragma unroll
                    for (int sub = 0; sub < 2; sub++) {
                        int nt = j * 2 + sub;
                        mma16816(s[nt], qhf[k16], kh[sub * 2], kh[sub * 2 + 1]);
                        mma16816(s[nt], qhf[k16], kl[sub * 2], kl[sub * 2 + 1]);
                        mma16816(s[nt], qlf[k16], kh[sub * 2], kh[sub * 2 + 1]);
                    }
                }
            }
            // scale + online softmax
            float mx0 = -1e30f, mx1 = -1e30f;
#pragma unroll
            for (int n = 0; n < 8; n++) {
#pragma unroll
                for (int i = 0; i < 4; i++) s[n][i] *= 0.125f;
                mx0 = fmaxf(mx0, fmaxf(s[n][0], s[n][1]));
                mx1 = fmaxf(mx1, fmaxf(s[n][2], s[n][3]));
            }
            mx0 = fmaxf(mx0, __shfl_xor_sync(~0u, mx0, 1));
            mx0 = fmaxf(mx0, __shfl_xor_sync(~0u, mx0, 2));
            mx1 = fmaxf(mx1, __shfl_xor_sync(~0u, mx1, 1));
            mx1 = fmaxf(mx1, __shfl_xor_sync(~0u, mx1, 2));
            float nm0 = fmaxf(m0, mx0), nm1 = fmaxf(m1, mx1);
            float cr0 = __expf(m0 - nm0), cr1 = __expf(m1 - nm1);
            float rs0 = 0.f, rs1 = 0.f;
#pragma unroll
            for (int n = 0; n < 8; n++) {
                s[n][0] = __expf(s[n][0] - nm0);
                s[n][1] = __expf(s[n][1] - nm0);
                s[n][2] = __expf(s[n][2] - nm1);
                s[n][3] = __expf(s[n][3] - nm1);
                rs0 += s[n][0] + s[n][1];
                rs1 += s[n][2] + s[n][3];
            }
            rs0 += __shfl_xor_sync(~0u, rs0, 1);
            rs0 += __shfl_xor_sync(~0u, rs0, 2);
            rs1 += __shfl_xor_sync(~0u, rs1, 1);
            rs1 += __shfl_xor_sync(~0u, rs1, 2);
            l0 = l0 * cr0 + rs0; l1 = l1 * cr1 + rs1;
            m0 = nm0; m1 = nm1;
#pragma unroll
            for (int n = 0; n < 8; n++) {
                accO[n][0] *= cr0; accO[n][1] *= cr0;
                accO[n][2] *= cr1; accO[n][3] *= cr1;
            }

            // O += P V — j2 outer so P fragments are only 8 regs live at a time
#pragma unroll
            for (int j2 = 0; j2 < 4; j2++) {
                uint32_t pa_hi[4], pa_lo[4];
                {
                    float x0, x1;
                    __nv_bfloat16 h0, h1;
                    x0 = s[2 * j2][0]; x1 = s[2 * j2][1];
                    h0 = __float2bfloat16(x0); h1 = __float2bfloat16(x1);
                    pa_hi[0] = (uint32_t)__bfloat16_as_ushort(h0) | ((uint32_t)__bfloat16_as_ushort(h1) << 16);
                    pa_lo[0] = pack_bf16(x0 - __bfloat162float(h0), x1 - __bfloat162float(h1));
                    x0 = s[2 * j2][2]; x1 = s[2 * j2][3];
                    h0 = __float2bfloat16(x0); h1 = __float2bfloat16(x1);
                    pa_hi[1] = (uint32_t)__bfloat16_as_ushort(h0) | ((uint32_t)__bfloat16_as_ushort(h1) << 16);
                    pa_lo[1] = pack_bf16(x0 - __bfloat162float(h0), x1 - __bfloat162float(h1));
                    x0 = s[2 * j2 + 1][0]; x1 = s[2 * j2 + 1][1];
                    h0 = __float2bfloat16(x0); h1 = __float2bfloat16(x1);
                    pa_hi[2] = (uint32_t)__bfloat16_as_ushort(h0) | ((uint32_t)__bfloat16_as_ushort(h1) << 16);
                    pa_lo[2] = pack_bf16(x0 - __bfloat162float(h0), x1 - __bfloat162float(h1));
                    x0 = s[2 * j2 + 1][2]; x1 = s[2 * j2 + 1][3];
                    h0 = __float2bfloat16(x0); h1 = __float2bfloat16(x1);
                    pa_hi[3] = (uint32_t)__bfloat16_as_ushort(h0) | ((uint32_t)__bfloat16_as_ushort(h1) << 16);
                    pa_lo[3] = pack_bf16(x0 - __bfloat162float(h0), x1 - __bfloat162float(h1));
                }
#pragma unroll
                for (int jd = 0; jd < 4; jd++) {
                    uint32_t vhf[4], vlf[4];
                    uint32_t off = (uint32_t)((j2 * 16 + v_row) * VPAD + jd * 16 + v_c8) * 2;
                    ldm_x4t(smb + AS_VHI + off, vhf);
                    ldm_x4t(smb + AS_VLO + off, vlf);
#pragma unroll
                    for (int sub = 0; sub < 2; sub++) {
                        int nt = jd * 2 + sub;
                        mma16816(accO[nt], pa_hi, vhf[sub * 2], vhf[sub * 2 + 1]);
                        mma16816(accO[nt], pa_hi, vlf[sub * 2], vlf[sub * 2 + 1]);
                        mma16816(accO[nt], pa_lo, vhf[sub * 2], vhf[sub * 2 + 1]);
                    }
                }
            }
        }

        // gate: reference broadcast quirk — out[p,b] weighted by layer_w[p][b]
        float lw = LW[p * NP + b];
        float f0 = lw / l0, f1 = lw / l1;
#pragma unroll
        for (int n = 0; n < 8; n++) {
            comb[n][0] += accO[n][0] * f0;
            comb[n][1] += accO[n][1] * f0;
            comb[n][2] += accO[n][2] * f1;
            comb[n][3] += accO[n][3] * f1;
        }
    }

    // write combined directly as split bf16 [b, s, hh*64 + d]
    const int row0 = s0 + wid * 16 + g;
#pragma unroll
    for (int n = 0; n < 8; n++) {
        int d = n * 8 + 2 * t;
        size_t o0 = ((size_t)(b * SEQ + row0)) * HID + hh * HD + d;
        size_t o1 = ((size_t)(b * SEQ + row0 + 8)) * HID + hh * HD + d;
        float x0 = comb[n][0], x1 = comb[n][1];
        __nv_bfloat16 h0 = __float2bfloat16(x0), h1 = __float2bfloat16(x1);
        *(uint32_t*)&Chi[o0] = (uint32_t)__bfloat16_as_ushort(h0) | ((uint32_t)__bfloat16_as_ushort(h1) << 16);
        *(uint32_t*)&Clo[o0] = pack_bf16(x0 - __bfloat162float(h0), x1 - __bfloat162float(h1));
        x0 = comb[n][2]; x1 = comb[n][3];
        h0 = __float2bfloat16(x0); h1 = __float2bfloat16(x1);
        *(uint32_t*)&Chi[o1] = (uint32_t)__bfloat16_as_ushort(h0) | ((uint32_t)__bfloat16_as_ushort(h1) << 16);
        *(uint32_t*)&Clo[o1] = pack_bf16(x0 - __bfloat162float(h0), x1 - __bfloat162float(h1));
    }
}

// ---------------- launcher ----------------
extern "C" void kernel_launch(void* const* d_in, const int* in_sizes, int n_in,
                              void* d_out, int out_size) {
    const float* hs   = (const float*)d_in[0];
    const float* prev = (const float*)d_in[1];
    const float* wq   = (const float*)d_in[2];
    const float* bq   = (const float*)d_in[3];
    const float* wk   = (const float*)d_in[4];
    const float* bk   = (const float*)d_in[5];
    const float* wv   = (const float*)d_in[6];
    const float* bv   = (const float*)d_in[7];
    const float* wo   = (const float*)d_in[8];
    const float* bo   = (const float*)d_in[9];
    const float* wg   = (const float*)d_in[10];
    float* out = (float*)d_out;

    float *pLW;
    __nv_bfloat16 *pPhi, *pPlo, *pHhi, *pHlo, *pChi, *pClo, *pWthi, *pWtlo;
    __nv_bfloat16 *pQhi, *pQlo, *pKhi, *pKlo, *pVhi, *pVlo;
    cudaGetSymbolAddress((void**)&pLW, g_LW);
    cudaGetSymbolAddress((void**)&pPhi, g_Phi);
    cudaGetSymbolAddress((void**)&pPlo, g_Plo);
    cudaGetSymbolAddress((void**)&pHhi, g_Hhi);
    cudaGetSymbolAddress((void**)&pHlo, g_Hlo);
    cudaGetSymbolAddress((void**)&pChi, g_Chi);
    cudaGetSymbolAddress((void**)&pClo, g_Clo);
    cudaGetSymbolAddress((void**)&pWthi, g_Wthi);
    cudaGetSymbolAddress((void**)&pWtlo, g_Wtlo);
    cudaGetSymbolAddress((void**)&pQhi, g_Qhi);
    cudaGetSymbolAddress((void**)&pQlo, g_Qlo);
    cudaGetSymbolAddress((void**)&pKhi, g_Khi);
    cudaGetSymbolAddress((void**)&pKlo, g_Klo);
    cudaGetSymbolAddress((void**)&pVhi, g_Vhi);
    cudaGetSymbolAddress((void**)&pVlo, g_Vlo);

    const size_t WSZ = (size_t)HID * HID;

    cudaFuncSetAttribute(gemm_hmma<0>, cudaFuncAttributeMaxDynamicSharedMemorySize, SM_END);
    cudaFuncSetAttribute(gemm_hmma<1>, cudaFuncAttributeMaxDynamicSharedMemorySize, SM_END);
    cudaFuncSetAttribute(gemm_hmma<2>, cudaFuncAttributeMaxDynamicSharedMemorySize, SM_END);
    cudaFuncSetAttribute(attn_hmma, cudaFuncAttributeMaxDynamicSharedMemorySize, AS_END);

    gating_kernel<<<BATCH, 1024>>>(hs, wg, pLW);

    int nH4 = BATCH * SEQ * HID / 4;
    int nP4 = NP * BATCH * SEQ * HID / 4;
    split_kernel<<<nH4 / 256, 256>>>(hs, pHhi, pHlo, nH4);
    split_kernel<<<nP4 / 256, 256>>>(prev, pPhi, pPlo, nP4);
    wsplit_kernel<<<dim3(32, 32), dim3(32, 8)>>>(wq, pWthi + 0 * WSZ, pWtlo + 0 * WSZ);
    wsplit_kernel<<<dim3(32, 32), dim3(32, 8)>>>(wk, pWthi + 1 * WSZ, pWtlo + 1 * WSZ);
    wsplit_kernel<<<dim3(32, 32), dim3(32, 8)>>>(wv, pWthi + 2 * WSZ, pWtlo + 2 * WSZ);
    wsplit_kernel<<<dim3(32, 32), dim3(32, 8)>>>(wo, pWthi + 3 * WSZ, pWtlo + 3 * WSZ);

    gemm_hmma<1><<<dim3(BATCH * SEQ / MT, HID / NT), 256, SM_END>>>(
        pHhi, pHlo, pWthi + 0 * WSZ, pWtlo + 0 * WSZ, bq, nullptr, pQhi, pQlo);
    gemm_hmma<1><<<dim3(NP * BATCH * SEQ / MT, HID / NT), 256, SM_END>>>(
        pPhi, pPlo, pWthi + 1 * WSZ, pWtlo + 1 * WSZ, bk, nullptr, pKhi, pKlo);
    gemm_hmma<2><<<dim3(NP * BATCH * SEQ / MT, HID / NT), 256, SM_END>>>(
        pPhi, pPlo, pWthi + 2 * WSZ, pWtlo + 2 * WSZ, bv, nullptr, pVhi, pVlo);

    attn_hmma<<<dim3(SEQ / 128, NH, BATCH), 256, AS_END>>>(
        pQhi, pQlo, pKhi, pKlo, pVhi, pVlo, pLW, pChi, pClo);

    gemm_hmma<0><<<dim3(BATCH * SEQ / MT, HID / NT), 256, SM_END>>>(
        pChi, pClo, pWthi + 3 * WSZ, pWtlo + 3 * WSZ, bo, out, nullptr, nullptr);
}

// round 11
// speedup vs baseline: 1.5845x; 1.5845x over previous
#include <cuda_runtime.h>
#include <cuda_bf16.h>
#include <math.h>
#include <stdint.h>

#define HID   1024
#define NH    16
#define HD    64
#define NP    4
#define BATCH 4
#define SEQ   1024

// ---------------- scratch (device globals; no allocation allowed) ----------------
__device__ float g_LW[BATCH * NP];

__device__ __nv_bfloat16 g_Phi[(size_t)NP * BATCH * SEQ * HID];
__device__ __nv_bfloat16 g_Plo[(size_t)NP * BATCH * SEQ * HID];
__device__ __nv_bfloat16 g_Hhi[(size_t)BATCH * SEQ * HID];
__device__ __nv_bfloat16 g_Hlo[(size_t)BATCH * SEQ * HID];
__device__ __nv_bfloat16 g_Chi[(size_t)BATCH * SEQ * HID];
__device__ __nv_bfloat16 g_Clo[(size_t)BATCH * SEQ * HID];
__device__ __nv_bfloat16 g_Wthi[4][(size_t)HID * HID];
__device__ __nv_bfloat16 g_Wtlo[4][(size_t)HID * HID];

__device__ __nv_bfloat16 g_Qhi[(size_t)BATCH * NH * SEQ * HD];
__device__ __nv_bfloat16 g_Qlo[(size_t)BATCH * NH * SEQ * HD];
__device__ __nv_bfloat16 g_Khi[(size_t)NP * BATCH * NH * SEQ * HD];
__device__ __nv_bfloat16 g_Klo[(size_t)NP * BATCH * NH * SEQ * HD];
__device__ __nv_bfloat16 g_Vhi[(size_t)NP * BATCH * NH * SEQ * HD];
__device__ __nv_bfloat16 g_Vlo[(size_t)NP * BATCH * NH * SEQ * HD];

// ---------------- helpers ----------------
static __device__ __forceinline__ uint32_t s2u(const void* p) {
    uint32_t a;
    asm("{ .reg .u64 t; cvta.to.shared.u64 t, %1; cvt.u32.u64 %0, t; }" : "=r"(a) : "l"(p));
    return a;
}
static __device__ __forceinline__ void ldm_x4(uint32_t addr, uint32_t r[4]) {
    asm volatile("ldmatrix.sync.aligned.m8n8.x4.shared.b16 {%0,%1,%2,%3}, [%4];"
                 : "=r"(r[0]), "=r"(r[1]), "=r"(r[2]), "=r"(r[3]) : "r"(addr));
}
static __device__ __forceinline__ void ldm_x4t(uint32_t addr, uint32_t r[4]) {
    asm volatile("ldmatrix.sync.aligned.m8n8.x4.trans.shared.b16 {%0,%1,%2,%3}, [%4];"
                 : "=r"(r[0]), "=r"(r[1]), "=r"(r[2]), "=r"(r[3]) : "r"(addr));
}
static __device__ __forceinline__ void mma16816(float* c, const uint32_t a[4],
                                                uint32_t b0, uint32_t b1) {
    asm volatile(
        "mma.sync.aligned.m16n8k16.row.col.f32.bf16.bf16.f32 "
        "{%0,%1,%2,%3}, {%4,%5,%6,%7}, {%8,%9}, {%0,%1,%2,%3};"
        : "+f"(c[0]), "+f"(c[1]), "+f"(c[2]), "+f"(c[3])
        : "r"(a[0]), "r"(a[1]), "r"(a[2]), "r"(a[3]), "r"(b0), "r"(b1));
}
static __device__ __forceinline__ uint32_t pack_bf16(float x, float y) {
    __nv_bfloat16 a = __float2bfloat16(x), b = __float2bfloat16(y);
    return (uint32_t)__bfloat16_as_ushort(a) | ((uint32_t)__bfloat16_as_ushort(b) << 16);
}
static __device__ __forceinline__ void cp16(uint32_t saddr, const void* g) {
    asm volatile("cp.async.cg.shared.global [%0], [%1], 16;" :: "r"(saddr), "l"(g));
}
#define CP_COMMIT() asm volatile("cp.async.commit_group;" ::: "memory")
#define CP_WAIT1()  asm volatile("cp.async.wait_group 1;" ::: "memory")
#define CP_WAIT0()  asm volatile("cp.async.wait_group 0;" ::: "memory")

// ---------------- gating ----------------
__global__ void gating_kernel(const float* __restrict__ hs,
                              const float* __restrict__ wg,
                              float* __restrict__ lw) {
    int b = blockIdx.x;
    int t = threadIdx.x;
    const float* p = hs + (size_t)b * SEQ * HID + t;
    float s = 0.f;
    for (int i = 0; i < SEQ; i++) s += p[(size_t)i * HID];
    s *= (1.0f / SEQ);

    float lg[NP];
#pragma unroll
    for (int k = 0; k < NP; k++) lg[k] = s * wg[t * NP + k];

    __shared__ float red[NP][32];
    int lane = t & 31, w = t >> 5;
#pragma unroll
    for (int k = 0; k < NP; k++) {
        float v = lg[k];
#pragma unroll
        for (int o = 16; o; o >>= 1) v += __shfl_xor_sync(~0u, v, o);
        if (lane == 0) red[k][w] = v;
    }
    __syncthreads();
    if (w == 0) {
#pragma unroll
        for (int k = 0; k < NP; k++) {
            float v = red[k][lane];
#pragma unroll
            for (int o = 16; o; o >>= 1) v += __shfl_xor_sync(~0u, v, o);
            if (lane == 0) red[k][0] = v;
        }
    }
    __syncthreads();
    if (t == 0) {
        float m = red[0][0];
#pragma unroll
        for (int k = 1; k < NP; k++) m = fmaxf(m, red[k][0]);
        float e[NP], se = 0.f;
#pragma unroll
        for (int k = 0; k < NP; k++) { e[k] = expf(red[k][0] - m); se += e[k]; }
        float inv = 1.0f / se;
#pragma unroll
        for (int k = 0; k < NP; k++) lw[b * NP + k] = e[k] * inv;
    }
}

// ---------------- fp32 -> (bf16 hi, bf16 lo) split ----------------
__global__ void split_kernel(const float* __restrict__ in,
                             __nv_bfloat16* __restrict__ hi,
                             __nv_bfloat16* __restrict__ lo, int n4) {
    int i = blockIdx.x * 256 + threadIdx.x;
    if (i >= n4) return;
    float4 v = ((const float4*)in)[i];
    float x[4] = {v.x, v.y, v.z, v.w};
    uint32_t ph[2], pl[2];
#pragma unroll
    for (int j = 0; j < 2; j++) {
        __nv_bfloat16 h0 = __float2bfloat16(x[2 * j]);
        __nv_bfloat16 h1 = __float2bfloat16(x[2 * j + 1]);
        __nv_bfloat16 l0 = __float2bfloat16(x[2 * j] - __bfloat162float(h0));
        __nv_bfloat16 l1 = __float2bfloat16(x[2 * j + 1] - __bfloat162float(h1));
        ph[j] = (uint32_t)__bfloat16_as_ushort(h0) | ((uint32_t)__bfloat16_as_ushort(h1) << 16);
        pl[j] = (uint32_t)__bfloat16_as_ushort(l0) | ((uint32_t)__bfloat16_as_ushort(l1) << 16);
    }
    ((uint2*)hi)[i] = make_uint2(ph[0], ph[1]);
    ((uint2*)lo)[i] = make_uint2(pl[0], pl[1]);
}

// ---------------- W [K,N] fp32 -> Wt [N,K] bf16 hi/lo ----------------
__global__ void wsplit_kernel(const float* __restrict__ W,
                              __nv_bfloat16* __restrict__ hi,
                              __nv_bfloat16* __restrict__ lo) {
    __shared__ float tile[32][33];
    int k0 = blockIdx.x * 32, n0 = blockIdx.y * 32;
    for (int j = threadIdx.y; j < 32; j += 8)
        tile[j][threadIdx.x] = W[(size_t)(k0 + j) * HID + n0 + threadIdx.x];
    __syncthreads();
    for (int j = threadIdx.y; j < 32; j += 8) {
        float x = tile[threadIdx.x][j];
        __nv_bfloat16 h = __float2bfloat16(x);
        __nv_bfloat16 l = __float2bfloat16(x - __bfloat162float(h));
        size_t o = (size_t)(n0 + j) * HID + k0 + threadIdx.x;
        hi[o] = h;
        lo[o] = l;
    }
}

// ---------------- HMMA split-bf16 GEMM, 128x128 tile, KC=32, cp.async 2-stage (R9) ----------------
#define MT 128
#define NT 128
#define KC 32
#define NCHUNK (HID / KC)
#define APAD 40

#define SM_BIAS  0
#define SM_INVF  512
#define SM_BUF   1024
#define ARR      (128 * APAD * 2)
#define OFF_AHI  0
#define OFF_ALO  ARR
#define OFF_BHI  (2 * ARR)
#define OFF_BLO  (3 * ARR)
#define STAGE    (4 * ARR)
#define SM_END   (SM_BUF + 2 * STAGE)  // 82944
#define SM_CS    SM_BUF

static __device__ __forceinline__ void gemm_issue(
    uint32_t sbase, int tid,
    const __nv_bfloat16* __restrict__ Ahi, const __nv_bfloat16* __restrict__ Alo,
    const __nv_bfloat16* __restrict__ Bhi, const __nv_bfloat16* __restrict__ Blo,
    size_t ab, size_t bb) {
#pragma unroll
    for (int it = 0; it < 2; it++) {
        int t2 = tid + it * 256;
        int r = t2 >> 2, e0 = (t2 & 3) * 8;
        uint32_t so = (uint32_t)(r * APAD + e0) * 2;
        size_t ga = ab + (size_t)r * HID + e0;
        size_t gb = bb + (size_t)r * HID + e0;
        cp16(sbase + OFF_AHI + so, Ahi + ga);
        cp16(sbase + OFF_ALO + so, Alo + ga);
        cp16(sbase + OFF_BHI + so, Bhi + gb);
        cp16(sbase + OFF_BLO + so, Blo + gb);
    }
    CP_COMMIT();
}

template <int MODE>
__global__ void __launch_bounds__(256, 2)
gemm_hmma(const __nv_bfloat16* __restrict__ Ahi, const __nv_bfloat16* __restrict__ Alo,
          const __nv_bfloat16* __restrict__ Bhi, const __nv_bfloat16* __restrict__ Blo,
          const float* __restrict__ bias, float* __restrict__ out,
          __nv_bfloat16* __restrict__ ohi, __nv_bfloat16* __restrict__ olo) {
    extern __shared__ __align__(16) char sm[];
    const uint32_t smb = s2u(sm);
    float* bsm  = (float*)(sm + SM_BIAS);
    float* invf = (float*)(sm + SM_INVF);

    const int tid = threadIdx.x;
    const int wid = tid >> 5, lane = tid & 31;
    const int g = lane >> 2, tig = lane & 3;
    const int warp_m = wid >> 2, warp_n = wid & 3;
    const int m_base = warp_m * 64, n_base = warp_n * 32;
    const int m0 = blockIdx.x * MT;
    const int col0 = blockIdx.y * NT;

    if (tid < 128) bsm[tid] = bias[col0 + tid];
    if (MODE == 1 && tid < 32)
        invf[tid] = powf(10000.0f, -(float)tid * (1.0f / 32.0f));

    float acc[4][4][4];
#pragma unroll
    for (int a = 0; a < 4; a++)
#pragma unroll
        for (int b = 0; b < 4; b++)
#pragma unroll
            for (int c = 0; c < 4; c++) acc[a][b][c] = 0.f;

    const int a_row = lane & 15, a_col8 = (lane >> 4) * 8;
    const int b_nrow = (lane & 7) + ((lane >> 4) << 3);
    const int b_k8 = ((lane >> 3) & 1) * 8;

    const size_t abase = (size_t)m0 * HID;
    const size_t bbase = (size_t)col0 * HID;

    gemm_issue(smb + SM_BUF, tid, Ahi, Alo, Bhi, Blo, abase, bbase);

    for (int kc = 0; kc < NCHUNK; kc++) {
        if (kc + 1 < NCHUNK) {
            gemm_issue(smb + SM_BUF + ((kc + 1) & 1) * STAGE, tid, Ahi, Alo, Bhi, Blo,
                       abase + (kc + 1) * KC, bbase + (kc + 1) * KC);
            CP_WAIT1();
        } else {
            CP_WAIT0();
        }
        __syncthreads();

        const uint32_t sb = smb + SM_BUF + (kc & 1) * STAGE;
#pragma unroll
        for (int k16 = 0; k16 < KC / 16; k16++) {
            uint32_t bhif[2][4], blof[2][4];
#pragma unroll
            for (int nt2 = 0; nt2 < 2; nt2++) {
                uint32_t off = (uint32_t)((n_base + nt2 * 16 + b_nrow) * APAD
                                          + k16 * 16 + b_k8) * 2;
                ldm_x4(sb + OFF_BHI + off, bhif[nt2]);
                ldm_x4(sb + OFF_BLO + off, blof[nt2]);
            }
#pragma unroll
            for (int mt = 0; mt < 4; mt++) {
                uint32_t ahif[4], alof[4];
                uint32_t off = (uint32_t)((m_base + mt * 16 + a_row) * APAD
                                          + k16 * 16 + a_col8) * 2;
                ldm_x4(sb + OFF_AHI + off, ahif);
                ldm_x4(sb + OFF_ALO + off, alof);
#pragma unroll
                for (int nt = 0; nt < 4; nt++) {
                    uint32_t b0h = bhif[nt >> 1][(nt & 1) * 2];
                    uint32_t b1h = bhif[nt >> 1][(nt & 1) * 2 + 1];
                    uint32_t b0l = blof[nt >> 1][(nt & 1) * 2];
                    uint32_t b1l = blof[nt >> 1][(nt & 1) * 2 + 1];
                    mma16816(acc[mt][nt], ahif, b0h, b1h);
                    mma16816(acc[mt][nt], ahif, b0l, b1l);
                    mma16816(acc[mt][nt], alof, b0h, b1h);
                }
            }
        }
        __syncthreads();
    }

    // ---------------- epilogue ----------------
    if (MODE == 1) {
        float* Cs = (float*)(sm + SM_CS);
#pragma unroll
        for (int mt = 0; mt < 4; mt++)
#pragma unroll
            for (int i2 = 0; i2 < 2; i2++) {
                int r = m_base + mt * 16 + g + i2 * 8;
#pragma unroll
                for (int nt = 0; nt < 4; nt++) {
                    int c = n_base + nt * 8 + 2 * tig;
                    Cs[r * 130 + c]     = acc[mt][nt][i2 * 2]     + bsm[c];
                    Cs[r * 130 + c + 1] = acc[mt][nt][i2 * 2 + 1] + bsm[c + 1];
                }
            }
        __syncthreads();
        const int seg = m0 >> 10;
        const int sbase2 = m0 & (SEQ - 1);
#pragma unroll
        for (int it = 0; it < 32; it++) {
            int idx = tid + it * 256;
            int r = idx >> 6, q = idx & 63;
            int h2 = q >> 5, d = q & 31;
            float c1 = Cs[r * 130 + h2 * 64 + d];
            float c2 = Cs[r * 130 + h2 * 64 + d + 32];
            int s = sbase2 + r;
            float sn, cs;
            sincosf((float)s * invf[d], &sn, &cs);
            int hh = blockIdx.y * 2 + h2;
            size_t base = ((size_t)(seg * NH + hh) * SEQ + s) << 6;
            float o1 = c1 * cs - c2 * sn;
            float o2 = c1 * sn + c2 * cs;
            __nv_bfloat16 h1 = __float2bfloat16(o1);
            __nv_bfloat16 h2b = __float2bfloat16(o2);
            ohi[base + d]      = h1;
            ohi[base + d + 32] = h2b;
            olo[base + d]      = __float2bfloat16(o1 - __bfloat162float(h1));
            olo[base + d + 32] = __float2bfloat16(o2 - __bfloat162float(h2b));
        }
    } else {
        const int seg = m0 >> 10;
        const int sbase2 = m0 & (SEQ - 1);
#pragma unroll
        for (int mt = 0; mt < 4; mt++)
#pragma unroll
            for (int i2 = 0; i2 < 2; i2++) {
                int rloc = m_base + mt * 16 + g + i2 * 8;
#pragma unroll
                for (int nt = 0; nt < 4; nt++) {
                    int c = n_base + nt * 8 + 2 * tig;
                    float vx = acc[mt][nt][i2 * 2]     + bsm[c];
                    float vy = acc[mt][nt][i2 * 2 + 1] + bsm[c + 1];
                    if (MODE == 0) {
                        *(float2*)&out[(size_t)(m0 + rloc) * HID + col0 + c] = make_float2(vx, vy);
                    } else {
                        int hh = blockIdx.y * 2 + (c >> 6);
                        int d = c & 63;
                        int s = sbase2 + rloc;
                        size_t off = (((size_t)(seg * NH + hh) * SEQ + s) << 6) + d;
                        __nv_bfloat16 hx = __float2bfloat16(vx);
                        __nv_bfloat16 hy = __float2bfloat16(vy);
                        uint32_t hp = (uint32_t)__bfloat16_as_ushort(hx) |
                                      ((uint32_t)__bfloat16_as_ushort(hy) << 16);
                        uint32_t lp = pack_bf16(vx - __bfloat162float(hx),
                                                vy - __bfloat162float(hy));
                        *(uint32_t*)&ohi[off] = hp;
                        *(uint32_t*)&olo[off] = lp;
                    }
                }
            }
    }
}

// ---------------- HMMA flash attention: (256,1), cp.async 2-stage KV, fused split out ----------------
#define VPAD 72
#define AQ_HI 0
#define AQ_LO (128 * VPAD * 2)
#define AKV   (2 * 128 * VPAD * 2)              // 36864
#define KARR  (64 * VPAD * 2)                   // 9216
#define KOFF_KHI 0
#define KOFF_KLO KARR
#define KOFF_VHI (2 * KARR)
#define KOFF_VLO (3 * KARR)
#define KSTAGE   (4 * KARR)                     // 36864
#define AS_END   (AKV + 2 * KSTAGE)             // 110592

static __device__ __forceinline__ void attn_issue(
    uint32_t sbase, int tid,
    const __nv_bfloat16* __restrict__ Khi, const __nv_bfloat16* __restrict__ Klo,
    const __nv_bfloat16* __restrict__ Vhi, const __nv_bfloat16* __restrict__ Vlo,
    size_t tb) {
#pragma unroll
    for (int it = 0; it < 2; it++) {
        int i = tid + it * 256;
        int r = i >> 3, c8 = (i & 7) * 8;
        uint32_t so = (uint32_t)(r * VPAD + c8) * 2;
        size_t go = tb + ((size_t)r << 6) + c8;
        cp16(sbase + KOFF_KHI + so, Khi + go);
        cp16(sbase + KOFF_KLO + so, Klo + go);
        cp16(sbase + KOFF_VHI + so, Vhi + go);
        cp16(sbase + KOFF_VLO + so, Vlo + go);
    }
    CP_COMMIT();
}

__global__ void __launch_bounds__(256, 1)
attn_hmma(const __nv_bfloat16* __restrict__ Qhi, const __nv_bfloat16* __restrict__ Qlo,
          const __nv_bfloat16* __restrict__ Khi, const __nv_bfloat16* __restrict__ Klo,
          const __nv_bfloat16* __restrict__ Vhi, const __nv_bfloat16* __restrict__ Vlo,
          const float* __restrict__ LW,
          __nv_bfloat16* __restrict__ Chi, __nv_bfloat16* __restrict__ Clo) {
    extern __shared__ __align__(16) char sm[];
    const uint32_t smb = s2u(sm);
    const int tid = threadIdx.x;
    const int wid = tid >> 5, lane = tid & 31;
    const int g = lane >> 2, t = lane & 3;
    const int qt = blockIdx.x, hh = blockIdx.y, b = blockIdx.z;
    const int s0 = qt * 128;

    // load Q tile (hi/lo)
    {
        const __nv_bfloat16* qh = Qhi + (((size_t)(b * NH + hh) * SEQ + s0) << 6);
        const __nv_bfloat16* ql = Qlo + (((size_t)(b * NH + hh) * SEQ + s0) << 6);
        for (int i = tid; i < 128 * 8; i += 256) {
            int r = i >> 3, c8 = (i & 7) * 8;
            uint32_t so = (uint32_t)(r * VPAD + c8) * 2;
            *(uint4*)(sm + AQ_HI + so) = *(const uint4*)(qh + ((size_t)r << 6) + c8);
            *(uint4*)(sm + AQ_LO + so) = *(const uint4*)(ql + ((size_t)r << 6) + c8);
        }
    }
    __syncthreads();

    // Q fragments resident in registers
    uint32_t qhf[4][4], qlf[4][4];
    {
        const int a_row = lane & 15, a_c8 = (lane >> 4) * 8;
#pragma unroll
        for (int k16 = 0; k16 < 4; k16++) {
            uint32_t off = (uint32_t)((wid * 16 + a_row) * VPAD + k16 * 16 + a_c8) * 2;
            ldm_x4(smb + AQ_HI + off, qhf[k16]);
            ldm_x4(smb + AQ_LO + off, qlf[k16]);
        }
    }

    const int b_nrow = (lane & 7) + ((lane >> 4) << 3);
    const int b_k8 = ((lane >> 3) & 1) * 8;
    const int v_row = (lane & 7) + (((lane >> 3) & 1) << 3);
    const int v_c8 = (lane >> 4) * 8;

    float comb[8][4];
#pragma unroll
    for (int n = 0; n < 8; n++)
#pragma unroll
        for (int i = 0; i < 4; i++) comb[n][i] = 0.f;

    for (int p = 0; p < NP; p++) {
        float m0 = -1e30f, m1 = -1e30f, l0 = 0.f, l1 = 0.f;
        float accO[8][4];
#pragma unroll
        for (int n = 0; n < 8; n++)
#pragma unroll
            for (int i = 0; i < 4; i++) accO[n][i] = 0.f;

        const size_t kvbase = ((size_t)((p * BATCH + b) * NH + hh) * SEQ) << 6;

        // prologue: prefetch tile 0 of this p
        attn_issue(smb + AKV, tid, Khi, Klo, Vhi, Vlo, kvbase);

        for (int kt = 0; kt < SEQ / 64; kt++) {
            if (kt + 1 < SEQ / 64) {
                attn_issue(smb + AKV + ((kt + 1) & 1) * KSTAGE, tid, Khi, Klo, Vhi, Vlo,
                           kvbase + ((size_t)((kt + 1) * 64) << 6));
                CP_WAIT1();
            } else {
                CP_WAIT0();
            }
            __syncthreads();

            const uint32_t sb = smb + AKV + (kt & 1) * KSTAGE;

            // S = Q K^T (3-term split)
            float s[8][4];
#pragma unroll
            for (int n = 0; n < 8; n++)
#pragma unroll
                for (int i = 0; i < 4; i++) s[n][i] = 0.f;
#pragma unroll
            for (int k16 = 0; k16 < 4; k16++) {
#pragma unroll
                for (int j = 0; j < 4; j++) {
                    uint32_t kh[4], kl[4];
                    uint32_t off = (uint32_t)((j * 16 + b_nrow) * VPAD + k16 * 16 + b_k8) * 2;
                    ldm_x4(sb + KOFF_KHI + off, kh);
                    ldm_x4(sb + KOFF_KLO + off, kl);
#pragma unroll
                    for (int sub = 0; sub < 2; sub++) {
                        int nt = j * 2 + sub;
                        mma16816(s[nt], qhf[k16], kh[sub * 2], kh[sub * 2 + 1]);
                        mma16816(s[nt], qhf[k16], kl[sub * 2], kl[sub * 2 + 1]);
                        mma16816(s[nt], qlf[k16], kh[sub * 2], kh[sub * 2 + 1]);
                    }
                }
            }
            // scale + online softmax
            float mx0 = -1e30f, mx1 = -1e30f;
#pragma unroll
            for (int n = 0; n < 8; n++) {
#pragma unroll
                for (int i = 0; i < 4; i++) s[n][i] *= 0.125f;
                mx0 = fmaxf(mx0, fmaxf(s[n][0], s[n][1]));
                mx1 = fmaxf(mx1, fmaxf(s[n][2], s[n][3]));
            }
            mx0 = fmaxf(mx0, __shfl_xor_sync(~0u, mx0, 1));
            mx0 = fmaxf(mx0, __shfl_xor_sync(~0u, mx0, 2));
            mx1 = fmaxf(mx1, __shfl_xor_sync(~0u, mx1, 1));
            mx1 = fmaxf(mx1, __shfl_xor_sync(~0u, mx1, 2));
            float nm0 = fmaxf(m0, mx0), nm1 = fmaxf(m1, mx1);
            float cr0 = __expf(m0 - nm0), cr1 = __expf(m1 - nm1);
            float rs0 = 0.f, rs1 = 0.f;
#pragma unroll
            for (int n = 0; n < 8; n++) {
                s[n][0] = __expf(s[n][0] - nm0);
                s[n][1] = __expf(s[n][1] - nm0);
                s[n][2] = __expf(s[n][2] - nm1);
                s[n][3] = __expf(s[n][3] - nm1);
                rs0 += s[n][0] + s[n][1];
                rs1 += s[n][2] + s[n][3];
            }
            rs0 += __shfl_xor_sync(~0u, rs0, 1);
            rs0 += __shfl_xor_sync(~0u, rs0, 2);
            rs1 += __shfl_xor_sync(~0u, rs1, 1);
            rs1 += __shfl_xor_sync(~0u, rs1, 2);
            l0 = l0 * cr0 + rs0; l1 = l1 * cr1 + rs1;
            m0 = nm0; m1 = nm1;
#pragma unroll
            for (int n = 0; n < 8; n++) {
                accO[n][0] *= cr0; accO[n][1] *= cr0;
                accO[n][2] *= cr1; accO[n][3] *= cr1;
            }

            // O += P V — j2 outer (8 live P regs)
#pragma unroll
            for (int j2 = 0; j2 < 4; j2++) {
                uint32_t pa_hi[4], pa_lo[4];
                {
                    float x0, x1;
                    __nv_bfloat16 h0, h1;
                    x0 = s[2 * j2][0]; x1 = s[2 * j2][1];
                    h0 = __float2bfloat16(x0); h1 = __float2bfloat16(x1);
                    pa_hi[0] = (uint32_t)__bfloat16_as_ushort(h0) | ((uint32_t)__bfloat16_as_ushort(h1) << 16);
                    pa_lo[0] = pack_bf16(x0 - __bfloat162float(h0), x1 - __bfloat162float(h1));
                    x0 = s[2 * j2][2]; x1 = s[2 * j2][3];
                    h0 = __float2bfloat16(x0); h1 = __float2bfloat16(x1);
                    pa_hi[1] = (uint32_t)__bfloat16_as_ushort(h0) | ((uint32_t)__bfloat16_as_ushort(h1) << 16);
                    pa_lo[1] = pack_bf16(x0 - __bfloat162float(h0), x1 - __bfloat162float(h1));
                    x0 = s[2 * j2 + 1][0]; x1 = s[2 * j2 + 1][1];
                    h0 = __float2bfloat16(x0); h1 = __float2bfloat16(x1);
                    pa_hi[2] = (uint32_t)__bfloat16_as_ushort(h0) | ((uint32_t)__bfloat16_as_ushort(h1) << 16);
                    pa_lo[2] = pack_bf16(x0 - __bfloat162float(h0), x1 - __bfloat162float(h1));
                    x0 = s[2 * j2 + 1][2]; x1 = s[2 * j2 + 1][3];
                    h0 = __float2bfloat16(x0); h1 = __float2bfloat16(x1);
                    pa_hi[3] = (uint32_t)__bfloat16_as_ushort(h0) | ((uint32_t)__bfloat16_as_ushort(h1) << 16);
                    pa_lo[3] = pack_bf16(x0 - __bfloat162float(h0), x1 - __bfloat162float(h1));
                }
#pragma unroll
                for (int jd = 0; jd < 4; jd++) {
                    uint32_t vhf[4], vlf[4];
                    uint32_t off = (uint32_t)((j2 * 16 + v_row) * VPAD + jd * 16 + v_c8) * 2;
                    ldm_x4t(sb + KOFF_VHI + off, vhf);
                    ldm_x4t(sb + KOFF_VLO + off, vlf);
#pragma unroll
                    for (int sub = 0; sub < 2; sub++) {
                        int nt = jd * 2 + sub;
                        mma16816(accO[nt], pa_hi, vhf[sub * 2], vhf[sub * 2 + 1]);
                        mma16816(accO[nt], pa_hi, vlf[sub * 2], vlf[sub * 2 + 1]);
                        mma16816(accO[nt], pa_lo, vhf[sub * 2], vhf[sub * 2 + 1]);
                    }
                }
            }
            __syncthreads();   // all warps done with this stage before it is re-filled
        }

        // gate: reference broadcast quirk — out[p,b] weighted by layer_w[p][b]
        float lw = LW[p * NP + b];
        float f0 = lw / l0, f1 = lw / l1;
#pragma unroll
        for (int n = 0; n < 8; n++) {
            comb[n][0] += accO[n][0] * f0;
            comb[n][1] += accO[n][1] * f0;
            comb[n][2] += accO[n][2] * f1;
            comb[n][3] += accO[n][3] * f1;
        }
    }

    // write combined directly as split bf16 [b, s, hh*64 + d]
    const int row0 = s0 + wid * 16 + g;
#pragma unroll
    for (int n = 0; n < 8; n++) {
        int d = n * 8 + 2 * t;
        size_t o0 = ((size_t)(b * SEQ + row0)) * HID + hh * HD + d;
        size_t o1 = ((size_t)(b * SEQ + row0 + 8)) * HID + hh * HD + d;
        float x0 = comb[n][0], x1 = comb[n][1];
        __nv_bfloat16 h0 = __float2bfloat16(x0), h1 = __float2bfloat16(x1);
        *(uint32_t*)&Chi[o0] = (uint32_t)__bfloat16_as_ushort(h0) | ((uint32_t)__bfloat16_as_ushort(h1) << 16);
        *(uint32_t*)&Clo[o0] = pack_bf16(x0 - __bfloat162float(h0), x1 - __bfloat162float(h1));
        x0 = comb[n][2]; x1 = comb[n][3];
        h0 = __float2bfloat16(x0); h1 = __float2bfloat16(x1);
        *(uint32_t*)&Chi[o1] = (uint32_t)__bfloat16_as_ushort(h0) | ((uint32_t)__bfloat16_as_ushort(h1) << 16);
        *(uint32_t*)&Clo[o1] = pack_bf16(x0 - __bfloat162float(h0), x1 - __bfloat162float(h1));
    }
}

// ---------------- launcher ----------------
extern "C" void kernel_launch(void* const* d_in, const int* in_sizes, int n_in,
                              void* d_out, int out_size) {
    const float* hs   = (const float*)d_in[0];
    const float* prev = (const float*)d_in[1];
    const float* wq   = (const float*)d_in[2];
    const float* bq   = (const float*)d_in[3];
    const float* wk   = (const float*)d_in[4];
    const float* bk   = (const float*)d_in[5];
    const float* wv   = (const float*)d_in[6];
    const float* bv   = (const float*)d_in[7];
    const float* wo   = (const float*)d_in[8];
    const float* bo   = (const float*)d_in[9];
    const float* wg   = (const float*)d_in[10];
    float* out = (float*)d_out;

    float *pLW;
    __nv_bfloat16 *pPhi, *pPlo, *pHhi, *pHlo, *pChi, *pClo, *pWthi, *pWtlo;
    __nv_bfloat16 *pQhi, *pQlo, *pKhi, *pKlo, *pVhi, *pVlo;
    cudaGetSymbolAddress((void**)&pLW, g_LW);
    cudaGetSymbolAddress((void**)&pPhi, g_Phi);
    cudaGetSymbolAddress((void**)&pPlo, g_Plo);
    cudaGetSymbolAddress((void**)&pHhi, g_Hhi);
    cudaGetSymbolAddress((void**)&pHlo, g_Hlo);
    cudaGetSymbolAddress((void**)&pChi, g_Chi);
    cudaGetSymbolAddress((void**)&pClo, g_Clo);
    cudaGetSymbolAddress((void**)&pWthi, g_Wthi);
    cudaGetSymbolAddress((void**)&pWtlo, g_Wtlo);
    cudaGetSymbolAddress((void**)&pQhi, g_Qhi);
    cudaGetSymbolAddress((void**)&pQlo, g_Qlo);
    cudaGetSymbolAddress((void**)&pKhi, g_Khi);
    cudaGetSymbolAddress((void**)&pKlo, g_Klo);
    cudaGetSymbolAddress((void**)&pVhi, g_Vhi);
    cudaGetSymbolAddress((void**)&pVlo, g_Vlo);

    const size_t WSZ = (size_t)HID * HID;

    cudaFuncSetAttribute(gemm_hmma<0>, cudaFuncAttributeMaxDynamicSharedMemorySize, SM_END);
    cudaFuncSetAttribute(gemm_hmma<1>, cudaFuncAttributeMaxDynamicSharedMemorySize, SM_END);
    cudaFuncSetAttribute(gemm_hmma<2>, cudaFuncAttributeMaxDynamicSharedMemorySize, SM_END);
    cudaFuncSetAttribute(attn_hmma, cudaFuncAttributeMaxDynamicSharedMemorySize, AS_END);

    gating_kernel<<<BATCH, 1024>>>(hs, wg, pLW);

    int nH4 = BATCH * SEQ * HID / 4;
    int nP4 = NP * BATCH * SEQ * HID / 4;
    split_kernel<<<nH4 / 256, 256>>>(hs, pHhi, pHlo, nH4);
    split_kernel<<<nP4 / 256, 256>>>(prev, pPhi, pPlo, nP4);
    wsplit_kernel<<<dim3(32, 32), dim3(32, 8)>>>(wq, pWthi + 0 * WSZ, pWtlo + 0 * WSZ);
    wsplit_kernel<<<dim3(32, 32), dim3(32, 8)>>>(wk, pWthi + 1 * WSZ, pWtlo + 1 * WSZ);
    wsplit_kernel<<<dim3(32, 32), dim3(32, 8)>>>(wv, pWthi + 2 * WSZ, pWtlo + 2 * WSZ);
    wsplit_kernel<<<dim3(32, 32), dim3(32, 8)>>>(wo, pWthi + 3 * WSZ, pWtlo + 3 * WSZ);

    gemm_hmma<1><<<dim3(BATCH * SEQ / MT, HID / NT), 256, SM_END>>>(
        pHhi, pHlo, pWthi + 0 * WSZ, pWtlo + 0 * WSZ, bq, nullptr, pQhi, pQlo);
    gemm_hmma<1><<<dim3(NP * BATCH * SEQ / MT, HID / NT), 256, SM_END>>>(
        pPhi, pPlo, pWthi + 1 * WSZ, pWtlo + 1 * WSZ, bk, nullptr, pKhi, pKlo);
    gemm_hmma<2><<<dim3(NP * BATCH * SEQ / MT, HID / NT), 256, SM_END>>>(
        pPhi, pPlo, pWthi + 2 * WSZ, pWtlo + 2 * WSZ, bv, nullptr, pVhi, pVlo);

    attn_hmma<<<dim3(SEQ / 128, NH, BATCH), 256, AS_END>>>(
        pQhi, pQlo, pKhi, pKlo, pVhi, pVlo, pLW, pChi, pClo);

    gemm_hmma<0><<<dim3(BATCH * SEQ / MT, HID / NT), 256, SM_END>>>(
        pChi, pClo, pWthi + 3 * WSZ, pWtlo + 3 * WSZ, bo, out, nullptr, nullptr);
}

// round 12
// speedup vs baseline: 1.6136x; 1.0184x over previous
#include <cuda_runtime.h>
#include <cuda_bf16.h>
#include <math.h>
#include <stdint.h>

#define HID   1024
#define NH    16
#define HD    64
#define NP    4
#define BATCH 4
#define SEQ   1024

// ---------------- scratch (device globals; no allocation allowed) ----------------
__device__ float g_LW[BATCH * NP];

__device__ __nv_bfloat16 g_Phi[(size_t)NP * BATCH * SEQ * HID];
__device__ __nv_bfloat16 g_Plo[(size_t)NP * BATCH * SEQ * HID];
__device__ __nv_bfloat16 g_Hhi[(size_t)BATCH * SEQ * HID];
__device__ __nv_bfloat16 g_Hlo[(size_t)BATCH * SEQ * HID];
__device__ __nv_bfloat16 g_Chi[(size_t)BATCH * SEQ * HID];
__device__ __nv_bfloat16 g_Clo[(size_t)BATCH * SEQ * HID];
__device__ __nv_bfloat16 g_Wthi[4][(size_t)HID * HID];
__device__ __nv_bfloat16 g_Wtlo[4][(size_t)HID * HID];

__device__ __nv_bfloat16 g_Qhi[(size_t)BATCH * NH * SEQ * HD];
__device__ __nv_bfloat16 g_Qlo[(size_t)BATCH * NH * SEQ * HD];
__device__ __nv_bfloat16 g_Khi[(size_t)NP * BATCH * NH * SEQ * HD];
__device__ __nv_bfloat16 g_Klo[(size_t)NP * BATCH * NH * SEQ * HD];
__device__ __nv_bfloat16 g_Vhi[(size_t)NP * BATCH * NH * SEQ * HD];
__device__ __nv_bfloat16 g_Vlo[(size_t)NP * BATCH * NH * SEQ * HD];

// ---------------- helpers ----------------
static __device__ __forceinline__ uint32_t s2u(const void* p) {
    uint32_t a;
    asm("{ .reg .u64 t; cvta.to.shared.u64 t, %1; cvt.u32.u64 %0, t; }" : "=r"(a) : "l"(p));
    return a;
}
static __device__ __forceinline__ void ldm_x4(uint32_t addr, uint32_t r[4]) {
    asm volatile("ldmatrix.sync.aligned.m8n8.x4.shared.b16 {%0,%1,%2,%3}, [%4];"
                 : "=r"(r[0]), "=r"(r[1]), "=r"(r[2]), "=r"(r[3]) : "r"(addr));
}
static __device__ __forceinline__ void ldm_x4t(uint32_t addr, uint32_t r[4]) {
    asm volatile("ldmatrix.sync.aligned.m8n8.x4.trans.shared.b16 {%0,%1,%2,%3}, [%4];"
                 : "=r"(r[0]), "=r"(r[1]), "=r"(r[2]), "=r"(r[3]) : "r"(addr));
}
static __device__ __forceinline__ void mma16816(float* c, const uint32_t a[4],
                                                uint32_t b0, uint32_t b1) {
    asm volatile(
        "mma.sync.aligned.m16n8k16.row.col.f32.bf16.bf16.f32 "
        "{%0,%1,%2,%3}, {%4,%5,%6,%7}, {%8,%9}, {%0,%1,%2,%3};"
        : "+f"(c[0]), "+f"(c[1]), "+f"(c[2]), "+f"(c[3])
        : "r"(a[0]), "r"(a[1]), "r"(a[2]), "r"(a[3]), "r"(b0), "r"(b1));
}
static __device__ __forceinline__ uint32_t pack_bf16(float x, float y) {
    __nv_bfloat16 a = __float2bfloat16(x), b = __float2bfloat16(y);
    return (uint32_t)__bfloat16_as_ushort(a) | ((uint32_t)__bfloat16_as_ushort(b) << 16);
}
static __device__ __forceinline__ void cp16(uint32_t saddr, const void* g) {
    asm volatile("cp.async.cg.shared.global [%0], [%1], 16;" :: "r"(saddr), "l"(g));
}
#define CP_COMMIT() asm volatile("cp.async.commit_group;" ::: "memory")
#define CP_WAIT1()  asm volatile("cp.async.wait_group 1;" ::: "memory")
#define CP_WAIT0()  asm volatile("cp.async.wait_group 0;" ::: "memory")

// ---------------- gating ----------------
__global__ void gating_kernel(const float* __restrict__ hs,
                              const float* __restrict__ wg,
                              float* __restrict__ lw) {
    int b = blockIdx.x;
    int t = threadIdx.x;
    const float* p = hs + (size_t)b * SEQ * HID + t;
    float s = 0.f;
    for (int i = 0; i < SEQ; i++) s += p[(size_t)i * HID];
    s *= (1.0f / SEQ);

    float lg[NP];
#pragma unroll
    for (int k = 0; k < NP; k++) lg[k] = s * wg[t * NP + k];

    __shared__ float red[NP][32];
    int lane = t & 31, w = t >> 5;
#pragma unroll
    for (int k = 0; k < NP; k++) {
        float v = lg[k];
#pragma unroll
        for (int o = 16; o; o >>= 1) v += __shfl_xor_sync(~0u, v, o);
        if (lane == 0) red[k][w] = v;
    }
    __syncthreads();
    if (w == 0) {
#pragma unroll
        for (int k = 0; k < NP; k++) {
            float v = red[k][lane];
#pragma unroll
            for (int o = 16; o; o >>= 1) v += __shfl_xor_sync(~0u, v, o);
            if (lane == 0) red[k][0] = v;
        }
    }
    __syncthreads();
    if (t == 0) {
        float m = red[0][0];
#pragma unroll
        for (int k = 1; k < NP; k++) m = fmaxf(m, red[k][0]);
        float e[NP], se = 0.f;
#pragma unroll
        for (int k = 0; k < NP; k++) { e[k] = expf(red[k][0] - m); se += e[k]; }
        float inv = 1.0f / se;
#pragma unroll
        for (int k = 0; k < NP; k++) lw[b * NP + k] = e[k] * inv;
    }
}

// ---------------- fp32 -> (bf16 hi, bf16 lo) split ----------------
__global__ void split_kernel(const float* __restrict__ in,
                             __nv_bfloat16* __restrict__ hi,
                             __nv_bfloat16* __restrict__ lo, int n4) {
    int i = blockIdx.x * 256 + threadIdx.x;
    if (i >= n4) return;
    float4 v = ((const float4*)in)[i];
    float x[4] = {v.x, v.y, v.z, v.w};
    uint32_t ph[2], pl[2];
#pragma unroll
    for (int j = 0; j < 2; j++) {
        __nv_bfloat16 h0 = __float2bfloat16(x[2 * j]);
        __nv_bfloat16 h1 = __float2bfloat16(x[2 * j + 1]);
        __nv_bfloat16 l0 = __float2bfloat16(x[2 * j] - __bfloat162float(h0));
        __nv_bfloat16 l1 = __float2bfloat16(x[2 * j + 1] - __bfloat162float(h1));
        ph[j] = (uint32_t)__bfloat16_as_ushort(h0) | ((uint32_t)__bfloat16_as_ushort(h1) << 16);
        pl[j] = (uint32_t)__bfloat16_as_ushort(l0) | ((uint32_t)__bfloat16_as_ushort(l1) << 16);
    }
    ((uint2*)hi)[i] = make_uint2(ph[0], ph[1]);
    ((uint2*)lo)[i] = make_uint2(pl[0], pl[1]);
}

// ---------------- W [K,N] fp32 -> Wt [N,K] bf16 hi/lo ----------------
__global__ void wsplit_kernel(const float* __restrict__ W,
                              __nv_bfloat16* __restrict__ hi,
                              __nv_bfloat16* __restrict__ lo) {
    __shared__ float tile[32][33];
    int k0 = blockIdx.x * 32, n0 = blockIdx.y * 32;
    for (int j = threadIdx.y; j < 32; j += 8)
        tile[j][threadIdx.x] = W[(size_t)(k0 + j) * HID + n0 + threadIdx.x];
    __syncthreads();
    for (int j = threadIdx.y; j < 32; j += 8) {
        float x = tile[threadIdx.x][j];
        __nv_bfloat16 h = __float2bfloat16(x);
        __nv_bfloat16 l = __float2bfloat16(x - __bfloat162float(h));
        size_t o = (size_t)(n0 + j) * HID + k0 + threadIdx.x;
        hi[o] = h;
        lo[o] = l;
    }
}

// ---------------- HMMA split-bf16 GEMM body (runtime mode), KC=32, cp.async 2-stage ----------------
#define MT 128
#define NT 128
#define KC 32
#define NCHUNK (HID / KC)
#define APAD 40

#define SM_BIAS  0
#define SM_INVF  512
#define SM_BUF   1024
#define ARR      (128 * APAD * 2)
#define OFF_AHI  0
#define OFF_ALO  ARR
#define OFF_BHI  (2 * ARR)
#define OFF_BLO  (3 * ARR)
#define STAGE    (4 * ARR)
#define SM_END   (SM_BUF + 2 * STAGE)  // 82944
#define SM_CS    SM_BUF

static __device__ __forceinline__ void gemm_issue(
    uint32_t sbase, int tid,
    const __nv_bfloat16* __restrict__ Ahi, const __nv_bfloat16* __restrict__ Alo,
    const __nv_bfloat16* __restrict__ Bhi, const __nv_bfloat16* __restrict__ Blo,
    size_t ab, size_t bb) {
#pragma unroll
    for (int it = 0; it < 2; it++) {
        int t2 = tid + it * 256;
        int r = t2 >> 2, e0 = (t2 & 3) * 8;
        uint32_t so = (uint32_t)(r * APAD + e0) * 2;
        size_t ga = ab + (size_t)r * HID + e0;
        size_t gb = bb + (size_t)r * HID + e0;
        cp16(sbase + OFF_AHI + so, Ahi + ga);
        cp16(sbase + OFF_ALO + so, Alo + ga);
        cp16(sbase + OFF_BHI + so, Bhi + gb);
        cp16(sbase + OFF_BLO + so, Blo + gb);
    }
    CP_COMMIT();
}

// mode 0: fp32 out[M,1024]; mode 1: RoPE + head-split -> hi/lo; mode 2: head-split -> hi/lo
static __device__ __forceinline__ void gemm_body(
    int mode, char* sm, const uint32_t smb,
    const __nv_bfloat16* __restrict__ Ahi, const __nv_bfloat16* __restrict__ Alo,
    const __nv_bfloat16* __restrict__ Bhi, const __nv_bfloat16* __restrict__ Blo,
    const float* __restrict__ bias, float* __restrict__ out,
    __nv_bfloat16* __restrict__ ohi, __nv_bfloat16* __restrict__ olo) {
    float* bsm  = (float*)(sm + SM_BIAS);
    float* invf = (float*)(sm + SM_INVF);

    const int tid = threadIdx.x;
    const int wid = tid >> 5, lane = tid & 31;
    const int g = lane >> 2, tig = lane & 3;
    const int warp_m = wid >> 2, warp_n = wid & 3;
    const int m_base = warp_m * 64, n_base = warp_n * 32;
    const int m0 = blockIdx.x * MT;
    const int col0 = blockIdx.y * NT;

    if (tid < 128) bsm[tid] = bias[col0 + tid];
    if (mode == 1 && tid < 32)
        invf[tid] = powf(10000.0f, -(float)tid * (1.0f / 32.0f));

    float acc[4][4][4];
#pragma unroll
    for (int a = 0; a < 4; a++)
#pragma unroll
        for (int b = 0; b < 4; b++)
#pragma unroll
            for (int c = 0; c < 4; c++) acc[a][b][c] = 0.f;

    const int a_row = lane & 15, a_col8 = (lane >> 4) * 8;
    const int b_nrow = (lane & 7) + ((lane >> 4) << 3);
    const int b_k8 = ((lane >> 3) & 1) * 8;

    const size_t abase = (size_t)m0 * HID;
    const size_t bbase = (size_t)col0 * HID;

    gemm_issue(smb + SM_BUF, tid, Ahi, Alo, Bhi, Blo, abase, bbase);

    for (int kc = 0; kc < NCHUNK; kc++) {
        if (kc + 1 < NCHUNK) {
            gemm_issue(smb + SM_BUF + ((kc + 1) & 1) * STAGE, tid, Ahi, Alo, Bhi, Blo,
                       abase + (kc + 1) * KC, bbase + (kc + 1) * KC);
            CP_WAIT1();
        } else {
            CP_WAIT0();
        }
        __syncthreads();

        const uint32_t sb = smb + SM_BUF + (kc & 1) * STAGE;
#pragma unroll
        for (int k16 = 0; k16 < KC / 16; k16++) {
            uint32_t bhif[2][4], blof[2][4];
#pragma unroll
            for (int nt2 = 0; nt2 < 2; nt2++) {
                uint32_t off = (uint32_t)((n_base + nt2 * 16 + b_nrow) * APAD
                                          + k16 * 16 + b_k8) * 2;
                ldm_x4(sb + OFF_BHI + off, bhif[nt2]);
                ldm_x4(sb + OFF_BLO + off, blof[nt2]);
            }
#pragma unroll
            for (int mt = 0; mt < 4; mt++) {
                uint32_t ahif[4], alof[4];
                uint32_t off = (uint32_t)((m_base + mt * 16 + a_row) * APAD
                                          + k16 * 16 + a_col8) * 2;
                ldm_x4(sb + OFF_AHI + off, ahif);
                ldm_x4(sb + OFF_ALO + off, alof);
                // term-outer ordering: same-acc reuse distance = 4 MMAs (covers RAW latency).
                // Per-accumulator FP order unchanged vs previous code (hh, hl, lh per k16).
#pragma unroll
                for (int nt = 0; nt < 4; nt++)   // Ahi @ Bhi
                    mma16816(acc[mt][nt], ahif,
                             bhif[nt >> 1][(nt & 1) * 2], bhif[nt >> 1][(nt & 1) * 2 + 1]);
#pragma unroll
                for (int nt = 0; nt < 4; nt++)   // Ahi @ Blo
                    mma16816(acc[mt][nt], ahif,
                             blof[nt >> 1][(nt & 1) * 2], blof[nt >> 1][(nt & 1) * 2 + 1]);
#pragma unroll
                for (int nt = 0; nt < 4; nt++)   // Alo @ Bhi
                    mma16816(acc[mt][nt], alof,
                             bhif[nt >> 1][(nt & 1) * 2], bhif[nt >> 1][(nt & 1) * 2 + 1]);
            }
        }
        __syncthreads();
    }

    // ---------------- epilogue ----------------
    if (mode == 1) {
        float* Cs = (float*)(sm + SM_CS);
#pragma unroll
        for (int mt = 0; mt < 4; mt++)
#pragma unroll
            for (int i2 = 0; i2 < 2; i2++) {
                int r = m_base + mt * 16 + g + i2 * 8;
#pragma unroll
                for (int nt = 0; nt < 4; nt++) {
                    int c = n_base + nt * 8 + 2 * tig;
                    Cs[r * 130 + c]     = acc[mt][nt][i2 * 2]     + bsm[c];
                    Cs[r * 130 + c + 1] = acc[mt][nt][i2 * 2 + 1] + bsm[c + 1];
                }
            }
        __syncthreads();
        const int seg = m0 >> 10;
        const int sbase2 = m0 & (SEQ - 1);
#pragma unroll
        for (int it = 0; it < 32; it++) {
            int idx = tid + it * 256;
            int r = idx >> 6, q = idx & 63;
            int h2 = q >> 5, d = q & 31;
            float c1 = Cs[r * 130 + h2 * 64 + d];
            float c2 = Cs[r * 130 + h2 * 64 + d + 32];
            int s = sbase2 + r;
            float sn, cs;
            sincosf((float)s * invf[d], &sn, &cs);
            int hh = blockIdx.y * 2 + h2;
            size_t base = ((size_t)(seg * NH + hh) * SEQ + s) << 6;
            float o1 = c1 * cs - c2 * sn;
            float o2 = c1 * sn + c2 * cs;
            __nv_bfloat16 h1 = __float2bfloat16(o1);
            __nv_bfloat16 h2b = __float2bfloat16(o2);
            ohi[base + d]      = h1;
            ohi[base + d + 32] = h2b;
            olo[base + d]      = __float2bfloat16(o1 - __bfloat162float(h1));
            olo[base + d + 32] = __float2bfloat16(o2 - __bfloat162float(h2b));
        }
    } else {
        const int seg = m0 >> 10;
        const int sbase2 = m0 & (SEQ - 1);
#pragma unroll
        for (int mt = 0; mt < 4; mt++)
#pragma unroll
            for (int i2 = 0; i2 < 2; i2++) {
                int rloc = m_base + mt * 16 + g + i2 * 8;
#pragma unroll
                for (int nt = 0; nt < 4; nt++) {
                    int c = n_base + nt * 8 + 2 * tig;
                    float vx = acc[mt][nt][i2 * 2]     + bsm[c];
                    float vy = acc[mt][nt][i2 * 2 + 1] + bsm[c + 1];
                    if (mode == 0) {
                        *(float2*)&out[(size_t)(m0 + rloc) * HID + col0 + c] = make_float2(vx, vy);
                    } else {
                        int hh = blockIdx.y * 2 + (c >> 6);
                        int d = c & 63;
                        int s = sbase2 + rloc;
                        size_t off = (((size_t)(seg * NH + hh) * SEQ + s) << 6) + d;
                        __nv_bfloat16 hx = __float2bfloat16(vx);
                        __nv_bfloat16 hy = __float2bfloat16(vy);
                        uint32_t hp = (uint32_t)__bfloat16_as_ushort(hx) |
                                      ((uint32_t)__bfloat16_as_ushort(hy) << 16);
                        uint32_t lp = pack_bf16(vx - __bfloat162float(hx),
                                                vy - __bfloat162float(hy));
                        *(uint32_t*)&ohi[off] = hp;
                        *(uint32_t*)&olo[off] = lp;
                    }
                }
            }
    }
}

// fused Q/K/V projection launch: grid (128, 8, 3); z selects operand set
__global__ void __launch_bounds__(256, 2)
qkv_hmma(const __nv_bfloat16* __restrict__ Hhi, const __nv_bfloat16* __restrict__ Hlo,
         const __nv_bfloat16* __restrict__ Phi, const __nv_bfloat16* __restrict__ Plo,
         const __nv_bfloat16* __restrict__ Wthi, const __nv_bfloat16* __restrict__ Wtlo,
         const float* __restrict__ bq, const float* __restrict__ bk, const float* __restrict__ bv,
         __nv_bfloat16* __restrict__ Qhi, __nv_bfloat16* __restrict__ Qlo,
         __nv_bfloat16* __restrict__ Khi, __nv_bfloat16* __restrict__ Klo,
         __nv_bfloat16* __restrict__ Vhi, __nv_bfloat16* __restrict__ Vlo) {
    extern __shared__ __align__(16) char sm[];
    const uint32_t smb = s2u(sm);
    const int z = blockIdx.z;
    const size_t WSZ = (size_t)HID * HID;

    const __nv_bfloat16 *Ahi, *Alo;
    const float* bias;
    __nv_bfloat16 *ohi, *olo;
    int mode, mxblocks;
    if (z == 0) {
        if (blockIdx.x >= BATCH * SEQ / MT) return;     // Q: 32 m-blocks
        Ahi = Hhi; Alo = Hlo; bias = bq; ohi = Qhi; olo = Qlo; mode = 1;
    } else if (z == 1) {
        Ahi = Phi; Alo = Plo; bias = bk; ohi = Khi; olo = Klo; mode = 1;
    } else {
        Ahi = Phi; Alo = Plo; bias = bv; ohi = Vhi; olo = Vlo; mode = 2;
    }
    gemm_body(mode, sm, smb, Ahi, Alo, Wthi + z * WSZ, Wtlo + z * WSZ,
              bias, nullptr, ohi, olo);
}

// output projection: grid (32, 8)
__global__ void __launch_bounds__(256, 2)
o_hmma(const __nv_bfloat16* __restrict__ Chi, const __nv_bfloat16* __restrict__ Clo,
       const __nv_bfloat16* __restrict__ Bhi, const __nv_bfloat16* __restrict__ Blo,
       const float* __restrict__ bias, float* __restrict__ out) {
    extern __shared__ __align__(16) char sm[];
    const uint32_t smb = s2u(sm);
    gemm_body(0, sm, smb, Chi, Clo, Bhi, Blo, bias, out, nullptr, nullptr);
}

// ---------------- HMMA flash attention: cp.async 2-stage KV, fused split out ----------------
#define VPAD 72
#define AQ_HI 0
#define AQ_LO (128 * VPAD * 2)
#define AKV   (2 * 128 * VPAD * 2)              // 36864
#define KARR  (64 * VPAD * 2)                   // 9216
#define KOFF_KHI 0
#define KOFF_KLO KARR
#define KOFF_VHI (2 * KARR)
#define KOFF_VLO (3 * KARR)
#define KSTAGE   (4 * KARR)                     // 36864
#define AS_END   (AKV + 2 * KSTAGE)             // 110592

static __device__ __forceinline__ void attn_issue(
    uint32_t sbase, int tid,
    const __nv_bfloat16* __restrict__ Khi, const __nv_bfloat16* __restrict__ Klo,
    const __nv_bfloat16* __restrict__ Vhi, const __nv_bfloat16* __restrict__ Vlo,
    size_t tb) {
#pragma unroll
    for (int it = 0; it < 2; it++) {
        int i = tid + it * 256;
        int r = i >> 3, c8 = (i & 7) * 8;
        uint32_t so = (uint32_t)(r * VPAD + c8) * 2;
        size_t go = tb + ((size_t)r << 6) + c8;
        cp16(sbase + KOFF_KHI + so, Khi + go);
        cp16(sbase + KOFF_KLO + so, Klo + go);
        cp16(sbase + KOFF_VHI + so, Vhi + go);
        cp16(sbase + KOFF_VLO + so, Vlo + go);
    }
    CP_COMMIT();
}

__global__ void __launch_bounds__(256, 1)
attn_hmma(const __nv_bfloat16* __restrict__ Qhi, const __nv_bfloat16* __restrict__ Qlo,
          const __nv_bfloat16* __restrict__ Khi, const __nv_bfloat16* __restrict__ Klo,
          const __nv_bfloat16* __restrict__ Vhi, const __nv_bfloat16* __restrict__ Vlo,
          const float* __restrict__ LW,
          __nv_bfloat16* __restrict__ Chi, __nv_bfloat16* __restrict__ Clo) {
    extern __shared__ __align__(16) char sm[];
    const uint32_t smb = s2u(sm);
    const int tid = threadIdx.x;
    const int wid = tid >> 5, lane = tid & 31;
    const int g = lane >> 2, t = lane & 3;
    const int qt = blockIdx.x, hh = blockIdx.y, b = blockIdx.z;
    const int s0 = qt * 128;

    // load Q tile (hi/lo)
    {
        const __nv_bfloat16* qh = Qhi + (((size_t)(b * NH + hh) * SEQ + s0) << 6);
        const __nv_bfloat16* ql = Qlo + (((size_t)(b * NH + hh) * SEQ + s0) << 6);
        for (int i = tid; i < 128 * 8; i += 256) {
            int r = i >> 3, c8 = (i & 7) * 8;
            uint32_t so = (uint32_t)(r * VPAD + c8) * 2;
            *(uint4*)(sm + AQ_HI + so) = *(const uint4*)(qh + ((size_t)r << 6) + c8);
            *(uint4*)(sm + AQ_LO + so) = *(const uint4*)(ql + ((size_t)r << 6) + c8);
        }
    }
    __syncthreads();

    uint32_t qhf[4][4], qlf[4][4];
    {
        const int a_row = lane & 15, a_c8 = (lane >> 4) * 8;
#pragma unroll
        for (int k16 = 0; k16 < 4; k16++) {
            uint32_t off = (uint32_t)((wid * 16 + a_row) * VPAD + k16 * 16 + a_c8) * 2;
            ldm_x4(smb + AQ_HI + off, qhf[k16]);
            ldm_x4(smb + AQ_LO + off, qlf[k16]);
        }
    }

    const int b_nrow = (lane & 7) + ((lane >> 4) << 3);
    const int b_k8 = ((lane >> 3) & 1) * 8;
    const int v_row = (lane & 7) + (((lane >> 3) & 1) << 3);
    const int v_c8 = (lane >> 4) * 8;

    float comb[8][4];
#pragma unroll
    for (int n = 0; n < 8; n++)
#pragma unroll
        for (int i = 0; i < 4; i++) comb[n][i] = 0.f;

    for (int p = 0; p < NP; p++) {
        float m0 = -1e30f, m1 = -1e30f, l0 = 0.f, l1 = 0.f;
        float accO[8][4];
#pragma unroll
        for (int n = 0; n < 8; n++)
#pragma unroll
            for (int i = 0; i < 4; i++) accO[n][i] = 0.f;

        const size_t kvbase = ((size_t)((p * BATCH + b) * NH + hh) * SEQ) << 6;

        attn_issue(smb + AKV, tid, Khi, Klo, Vhi, Vlo, kvbase);

        for (int kt = 0; kt < SEQ / 64; kt++) {
            if (kt + 1 < SEQ / 64) {
                attn_issue(smb + AKV + ((kt + 1) & 1) * KSTAGE, tid, Khi, Klo, Vhi, Vlo,
                           kvbase + ((size_t)((kt + 1) * 64) << 6));
                CP_WAIT1();
            } else {
                CP_WAIT0();
            }
            __syncthreads();

            const uint32_t sb = smb + AKV + (kt & 1) * KSTAGE;

            // S = Q K^T (3-term split), term-outer per j for RAW distance 2
            float s[8][4];
#pragma unroll
            for (int n = 0; n < 8; n++)
#pragma unroll
                for (int i = 0; i < 4; i++) s[n][i] = 0.f;
#pragma unroll
            for (int k16 = 0; k16 < 4; k16++) {
#pragma unroll
                for (int j = 0; j < 4; j++) {
                    uint32_t kh[4], kl[4];
                    uint32_t off = (uint32_t)((j * 16 + b_nrow) * VPAD + k16 * 16 + b_k8) * 2;
                    ldm_x4(sb + KOFF_KHI + off, kh);
                    ldm_x4(sb + KOFF_KLO + off, kl);
#pragma unroll
                    for (int sub = 0; sub < 2; sub++)
                        mma16816(s[j * 2 + sub], qhf[k16], kh[sub * 2], kh[sub * 2 + 1]);
#pragma unroll
                    for (int sub = 0; sub < 2; sub++)
                        mma16816(s[j * 2 + sub], qhf[k16], kl[sub * 2], kl[sub * 2 + 1]);
#pragma unroll
                    for (int sub = 0; sub < 2; sub++)
                        mma16816(s[j * 2 + sub], qlf[k16], kh[sub * 2], kh[sub * 2 + 1]);
                }
            }
            // scale + online softmax
            float mx0 = -1e30f, mx1 = -1e30f;
#pragma unroll
            for (int n = 0; n < 8; n++) {
#pragma unroll
                for (int i = 0; i < 4; i++) s[n][i] *= 0.125f;
                mx0 = fmaxf(mx0, fmaxf(s[n][0], s[n][1]));
                mx1 = fmaxf(mx1, fmaxf(s[n][2], s[n][3]));
            }
            mx0 = fmaxf(mx0, __shfl_xor_sync(~0u, mx0, 1));
            mx0 = fmaxf(mx0, __shfl_xor_sync(~0u, mx0, 2));
            mx1 = fmaxf(mx1, __shfl_xor_sync(~0u, mx1, 1));
            mx1 = fmaxf(mx1, __shfl_xor_sync(~0u, mx1, 2));
            float nm0 = fmaxf(m0, mx0), nm1 = fmaxf(m1, mx1);
            float cr0 = __expf(m0 - nm0), cr1 = __expf(m1 - nm1);
            float rs0 = 0.f, rs1 = 0.f;
#pragma unroll
            for (int n = 0; n < 8; n++) {
                s[n][0] = __expf(s[n][0] - nm0);
                s[n][1] = __expf(s[n][1] - nm0);
                s[n][2] = __expf(s[n][2] - nm1);
                s[n][3] = __expf(s[n][3] - nm1);
                rs0 += s[n][0] + s[n][1];
                rs1 += s[n][2] + s[n][3];
            }
            rs0 += __shfl_xor_sync(~0u, rs0, 1);
            rs0 += __shfl_xor_sync(~0u, rs0, 2);
            rs1 += __shfl_xor_sync(~0u, rs1, 1);
            rs1 += __shfl_xor_sync(~0u, rs1, 2);
            l0 = l0 * cr0 + rs0; l1 = l1 * cr1 + rs1;
            m0 = nm0; m1 = nm1;
#pragma unroll
            for (int n = 0; n < 8; n++) {
                accO[n][0] *= cr0; accO[n][1] *= cr0;
                accO[n][2] *= cr1; accO[n][3] *= cr1;
            }

            // O += P V — j2 outer, term-outer per (jd) for RAW distance 2
#pragma unroll
            for (int j2 = 0; j2 < 4; j2++) {
                uint32_t pa_hi[4], pa_lo[4];
                {
                    float x0, x1;
                    __nv_bfloat16 h0, h1;
                    x0 = s[2 * j2][0]; x1 = s[2 * j2][1];
                    h0 = __float2bfloat16(x0); h1 = __float2bfloat16(x1);
                    pa_hi[0] = (uint32_t)__bfloat16_as_ushort(h0) | ((uint32_t)__bfloat16_as_ushort(h1) << 16);
                    pa_lo[0] = pack_bf16(x0 - __bfloat162float(h0), x1 - __bfloat162float(h1));
                    x0 = s[2 * j2][2]; x1 = s[2 * j2][3];
                    h0 = __float2bfloat16(x0); h1 = __float2bfloat16(x1);
                    pa_hi[1] = (uint32_t)__bfloat16_as_ushort(h0) | ((uint32_t)__bfloat16_as_ushort(h1) << 16);
                    pa_lo[1] = pack_bf16(x0 - __bfloat162float(h0), x1 - __bfloat162float(h1));
                    x0 = s[2 * j2 + 1][0]; x1 = s[2 * j2 + 1][1];
                    h0 = __float2bfloat16(x0); h1 = __float2bfloat16(x1);
                    pa_hi[2] = (uint32_t)__bfloat16_as_ushort(h0) | ((uint32_t)__bfloat16_as_ushort(h1) << 16);
                    pa_lo[2] = pack_bf16(x0 - __bfloat162float(h0), x1 - __bfloat162float(h1));
                    x0 = s[2 * j2 + 1][2]; x1 = s[2 * j2 + 1][3];
                    h0 = __float2bfloat16(x0); h1 = __float2bfloat16(x1);
                    pa_hi[3] = (uint32_t)__bfloat16_as_ushort(h0) | ((uint32_t)__bfloat16_as_ushort(h1) << 16);
                    pa_lo[3] = pack_bf16(x0 - __bfloat162float(h0), x1 - __bfloat162float(h1));
                }
#pragma unroll
                for (int jd = 0; jd < 4; jd++) {
                    uint32_t vhf[4], vlf[4];
                    uint32_t off = (uint32_t)((j2 * 16 + v_row) * VPAD + jd * 16 + v_c8) * 2;
                    ldm_x4t(sb + KOFF_VHI + off, vhf);
                    ldm_x4t(sb + KOFF_VLO + off, vlf);
#pragma unroll
                    for (int sub = 0; sub < 2; sub++)
                        mma16816(accO[jd * 2 + sub], pa_hi, vhf[sub * 2], vhf[sub * 2 + 1]);
#pragma unroll
                    for (int sub = 0; sub < 2; sub++)
                        mma16816(accO[jd * 2 + sub], pa_hi, vlf[sub * 2], vlf[sub * 2 + 1]);
#pragma unroll
                    for (int sub = 0; sub < 2; sub++)
                        mma16816(accO[jd * 2 + sub], pa_lo, vhf[sub * 2], vhf[sub * 2 + 1]);
                }
            }
            __syncthreads();
        }

        // gate: reference broadcast quirk — out[p,b] weighted by layer_w[p][b]
        float lw = LW[p * NP + b];
        float f0 = lw / l0, f1 = lw / l1;
#pragma unroll
        for (int n = 0; n < 8; n++) {
            comb[n][0] += accO[n][0] * f0;
            comb[n][1] += accO[n][1] * f0;
            comb[n][2] += accO[n][2] * f1;
            comb[n][3] += accO[n][3] * f1;
        }
    }

    // write combined directly as split bf16 [b, s, hh*64 + d]
    const int row0 = s0 + wid * 16 + g;
#pragma unroll
    for (int n = 0; n < 8; n++) {
        int d = n * 8 + 2 * t;
        size_t o0 = ((size_t)(b * SEQ + row0)) * HID + hh * HD + d;
        size_t o1 = ((size_t)(b * SEQ + row0 + 8)) * HID + hh * HD + d;
        float x0 = comb[n][0], x1 = comb[n][1];
        __nv_bfloat16 h0 = __float2bfloat16(x0), h1 = __float2bfloat16(x1);
        *(uint32_t*)&Chi[o0] = (uint32_t)__bfloat16_as_ushort(h0) | ((uint32_t)__bfloat16_as_ushort(h1) << 16);
        *(uint32_t*)&Clo[o0] = pack_bf16(x0 - __bfloat162float(h0), x1 - __bfloat162float(h1));
        x0 = comb[n][2]; x1 = comb[n][3];
        h0 = __float2bfloat16(x0); h1 = __float2bfloat16(x1);
        *(uint32_t*)&Chi[o1] = (uint32_t)__bfloat16_as_ushort(h0) | ((uint32_t)__bfloat16_as_ushort(h1) << 16);
        *(uint32_t*)&Clo[o1] = pack_bf16(x0 - __bfloat162float(h0), x1 - __bfloat162float(h1));
    }
}

// ---------------- launcher ----------------
extern "C" void kernel_launch(void* const* d_in, const int* in_sizes, int n_in,
                              void* d_out, int out_size) {
    const float* hs   = (const float*)d_in[0];
    const float* prev = (const float*)d_in[1];
    const float* wq   = (const float*)d_in[2];
    const float* bq   = (const float*)d_in[3];
    const float* wk   = (const float*)d_in[4];
    const float* bk   = (const float*)d_in[5];
    const float* wv   = (const float*)d_in[6];
    const float* bv   = (const float*)d_in[7];
    const float* wo   = (const float*)d_in[8];
    const float* bo   = (const float*)d_in[9];
    const float* wg   = (const float*)d_in[10];
    float* out = (float*)d_out;

    float *pLW;
    __nv_bfloat16 *pPhi, *pPlo, *pHhi, *pHlo, *pChi, *pClo, *pWthi, *pWtlo;
    __nv_bfloat16 *pQhi, *pQlo, *pKhi, *pKlo, *pVhi, *pVlo;
    cudaGetSymbolAddress((void**)&pLW, g_LW);
    cudaGetSymbolAddress((void**)&pPhi, g_Phi);
    cudaGetSymbolAddress((void**)&pPlo, g_Plo);
    cudaGetSymbolAddress((void**)&pHhi, g_Hhi);
    cudaGetSymbolAddress((void**)&pHlo, g_Hlo);
    cudaGetSymbolAddress((void**)&pChi, g_Chi);
    cudaGetSymbolAddress((void**)&pClo, g_Clo);
    cudaGetSymbolAddress((void**)&pWthi, g_Wthi);
    cudaGetSymbolAddress((void**)&pWtlo, g_Wtlo);
    cudaGetSymbolAddress((void**)&pQhi, g_Qhi);
    cudaGetSymbolAddress((void**)&pQlo, g_Qlo);
    cudaGetSymbolAddress((void**)&pKhi, g_Khi);
    cudaGetSymbolAddress((void**)&pKlo, g_Klo);
    cudaGetSymbolAddress((void**)&pVhi, g_Vhi);
    cudaGetSymbolAddress((void**)&pVlo, g_Vlo);

    const size_t WSZ = (size_t)HID * HID;

    cudaFuncSetAttribute(qkv_hmma, cudaFuncAttributeMaxDynamicSharedMemorySize, SM_END);
    cudaFuncSetAttribute(o_hmma, cudaFuncAttributeMaxDynamicSharedMemorySize, SM_END);
    cudaFuncSetAttribute(attn_hmma, cudaFuncAttributeMaxDynamicSharedMemorySize, AS_END);

    gating_kernel<<<BATCH, 1024>>>(hs, wg, pLW);

    int nH4 = BATCH * SEQ * HID / 4;
    int nP4 = NP * BATCH * SEQ * HID / 4;
    split_kernel<<<nH4 / 256, 256>>>(hs, pHhi, pHlo, nH4);
    split_kernel<<<nP4 / 256, 256>>>(prev, pPhi, pPlo, nP4);
    wsplit_kernel<<<dim3(32, 32), dim3(32, 8)>>>(wq, pWthi + 0 * WSZ, pWtlo + 0 * WSZ);
    wsplit_kernel<<<dim3(32, 32), dim3(32, 8)>>>(wk, pWthi + 1 * WSZ, pWtlo + 1 * WSZ);
    wsplit_kernel<<<dim3(32, 32), dim3(32, 8)>>>(wv, pWthi + 2 * WSZ, pWtlo + 2 * WSZ);
    wsplit_kernel<<<dim3(32, 32), dim3(32, 8)>>>(wo, pWthi + 3 * WSZ, pWtlo + 3 * WSZ);

    // fused Q/K/V projections: one launch, better wave packing
    qkv_hmma<<<dim3(NP * BATCH * SEQ / MT, HID / NT, 3), 256, SM_END>>>(
        pHhi, pHlo, pPhi, pPlo, pWthi, pWtlo, bq, bk, bv,
        pQhi, pQlo, pKhi, pKlo, pVhi, pVlo);

    attn_hmma<<<dim3(SEQ / 128, NH, BATCH), 256, AS_END>>>(
        pQhi, pQlo, pKhi, pKlo, pVhi, pVlo, pLW, pChi, pClo);

    o_hmma<<<dim3(BATCH * SEQ / MT, HID / NT), 256, SM_END>>>(
        pChi, pClo, pWthi + 3 * WSZ, pWtlo + 3 * WSZ, bo, out);
}